// round 1
// baseline (speedup 1.0000x reference)
#include <cuda_runtime.h>
#include <cuda_bf16.h>
#include <math.h>

// Problem constants
#define D_NODE 256
#define D_PAIR 128
#define CC     32
#define NHEAD  8
#define NSEQ   128
#define NRES   256
#define NROWS  (NSEQ * NRES)          // 32768
#define EPROJ  1024                    // 768 qkv + 256 gate

// Scratch (static device allocations are the sanctioned mechanism)
__device__ float g_M[(size_t)NROWS * D_NODE];        // 33.5 MB  LN(M_raw)
__device__ float g_proj[(size_t)NROWS * EPROJ];      // 134 MB   q|k|v|gate_logits
__device__ float g_pb[(size_t)NHEAD * NRES * NRES];  // 2 MB     pair bias [h][k][q]
__device__ float g_wa[(size_t)NROWS * D_NODE];       // 33.5 MB  attention output

__device__ __forceinline__ float warp_sum(float v) {
#pragma unroll
    for (int o = 16; o > 0; o >>= 1) v += __shfl_xor_sync(0xffffffffu, v, o);
    return v;
}

// ---------------------------------------------------------------------------
// Kernel 1: LayerNorm over D_NODE=256, one block per row
// ---------------------------------------------------------------------------
__global__ __launch_bounds__(256) void ln_m_kernel(
    const float* __restrict__ x, const float* __restrict__ sc,
    const float* __restrict__ bi)
{
    __shared__ float red[16];
    int row = blockIdx.x;
    int tid = threadIdx.x;
    float v = x[(size_t)row * 256 + tid];
    float s1 = warp_sum(v);
    float s2 = warp_sum(v * v);
    if ((tid & 31) == 0) { red[tid >> 5] = s1; red[8 + (tid >> 5)] = s2; }
    __syncthreads();
    if (tid == 0) {
        float a = 0.f, b = 0.f;
#pragma unroll
        for (int i = 0; i < 8; i++) { a += red[i]; b += red[8 + i]; }
        red[0] = a; red[8] = b;
    }
    __syncthreads();
    float mu  = red[0] * (1.0f / 256.0f);
    float var = red[8] * (1.0f / 256.0f) - mu * mu;
    float inv = rsqrtf(var + 1e-5f);
    g_M[(size_t)row * 256 + tid] = (v - mu) * inv * sc[tid] + bi[tid];
}

// ---------------------------------------------------------------------------
// Kernel 2: LN(Z) + pair bias.  One block per (q,k); writes pb[h][k][q]
// (transposed so attention reads are coalesced over q=threadIdx).
// ---------------------------------------------------------------------------
__global__ __launch_bounds__(128) void pair_kernel(
    const float* __restrict__ Z, const float* __restrict__ sc,
    const float* __restrict__ bi, const float* __restrict__ Wb)
{
    __shared__ float red[8];
    __shared__ float zn[128];
    int bid = blockIdx.x;          // = q*256 + k  (Z row)
    int q = bid >> 8, k = bid & 255;
    int tid = threadIdx.x;
    float v = Z[(size_t)bid * 128 + tid];
    float s1 = warp_sum(v);
    float s2 = warp_sum(v * v);
    if ((tid & 31) == 0) { red[tid >> 5] = s1; red[4 + (tid >> 5)] = s2; }
    __syncthreads();
    if (tid == 0) {
        float a = 0.f, b = 0.f;
#pragma unroll
        for (int i = 0; i < 4; i++) { a += red[i]; b += red[4 + i]; }
        red[0] = a; red[4] = b;
    }
    __syncthreads();
    float mu  = red[0] * (1.0f / 128.0f);
    float var = red[4] * (1.0f / 128.0f) - mu * mu;
    zn[tid] = (v - mu) * rsqrtf(var + 1e-5f) * sc[tid] + bi[tid];
    __syncthreads();
    int w = tid >> 5, l = tid & 31;
#pragma unroll
    for (int j = 0; j < 2; j++) {
        int h = w * 2 + j;
        const float* wb = Wb + h * 128;
        float p = zn[l] * wb[l] + zn[l + 32] * wb[l + 32]
                + zn[l + 64] * wb[l + 64] + zn[l + 96] * wb[l + 96];
        p = warp_sum(p);
        if (l == 0) g_pb[(size_t)(h * 256 + k) * 256 + q] = p;
    }
}

// ---------------------------------------------------------------------------
// Kernel 3: proj = M @ [W_qkv; W_gate]^T   (NT gemm, K=256, N=1024)
// 64x64 tile, BK=16, 256 threads, 4x4 microtile
// ---------------------------------------------------------------------------
__global__ __launch_bounds__(256) void gemm_proj(
    const float* __restrict__ Wq, const float* __restrict__ Wg)
{
    __shared__ float As[64][16];
    __shared__ float Bs[64][17];
    int tid = threadIdx.x;
    int tx = tid & 15, ty = tid >> 4;
    int bm = blockIdx.y * 64, bn = blockIdx.x * 64;
    int lr = tid >> 2;
    int lc = (tid & 3) * 4;
    int e0 = bn + lr;
    const float* Brow = (e0 < 768) ? (Wq + (size_t)e0 * 256)
                                   : (Wg + (size_t)(e0 - 768) * 256);
    const float* Arow = g_M + (size_t)(bm + lr) * 256;
    float acc[4][4] = {};
    for (int k0 = 0; k0 < 256; k0 += 16) {
        float4 a4 = *(const float4*)(Arow + k0 + lc);
        float4 b4 = *(const float4*)(Brow + k0 + lc);
        *(float4*)&As[lr][lc] = a4;
        Bs[lr][lc] = b4.x; Bs[lr][lc + 1] = b4.y;
        Bs[lr][lc + 2] = b4.z; Bs[lr][lc + 3] = b4.w;
        __syncthreads();
#pragma unroll
        for (int kk = 0; kk < 16; kk++) {
            float a[4], b[4];
#pragma unroll
            for (int i = 0; i < 4; i++) a[i] = As[ty + 16 * i][kk];
#pragma unroll
            for (int j = 0; j < 4; j++) b[j] = Bs[tx + 16 * j][kk];
#pragma unroll
            for (int i = 0; i < 4; i++)
#pragma unroll
                for (int j = 0; j < 4; j++) acc[i][j] += a[i] * b[j];
        }
        __syncthreads();
    }
#pragma unroll
    for (int i = 0; i < 4; i++)
#pragma unroll
        for (int j = 0; j < 4; j++)
            g_proj[(size_t)(bm + ty + 16 * i) * EPROJ + bn + tx + 16 * j] = acc[i][j];
}

// ---------------------------------------------------------------------------
// Kernel 4: attention.  block=(h,s), 256 threads; thread owns one q-row.
// Online softmax (single pass).  K/V/Q staged in dynamic smem.
// ---------------------------------------------------------------------------
#define SMEM_ATTN ((8192 + 8192 + 256 * 33 + 256) * 4)

__global__ __launch_bounds__(256) void attn_kernel(const float* __restrict__ mask)
{
    extern __shared__ float sm[];
    float* Ks = sm;                 // [256][32]
    float* Vs = sm + 8192;          // [256][32]
    float* Qs = sm + 16384;         // [256][33] padded
    float* mb = sm + 16384 + 256 * 33;
    int h = blockIdx.x, s = blockIdx.y;
    int tid = threadIdx.x;
    const float* base = g_proj + (size_t)s * 256 * EPROJ;
#pragma unroll 4
    for (int idx = tid; idx < 8192; idx += 256) {
        int r = idx >> 5, c = idx & 31;
        int ro = r * EPROJ + h * 32 + c;
        Qs[r * 33 + c] = base[ro];
        Ks[idx]        = base[ro + 256];
        Vs[idx]        = base[ro + 512];
    }
    mb[tid] = 1e9f * (mask[s * 256 + tid] - 1.0f);
    __syncthreads();

    int q = tid;
    float qr[32];
    const float scale = 0.17677669529663688f;   // 1/sqrt(32)
#pragma unroll
    for (int c = 0; c < 32; c++) qr[c] = Qs[q * 33 + c] * scale;

    float m = -1e30f, ssum = 0.f;
    float acc[32] = {};
    const float* pbh = g_pb + (size_t)(h * 256) * 256 + q;
#pragma unroll 1
    for (int k = 0; k < 256; k++) {
        float l = mb[k] + pbh[k * 256];
        const float* kr = Ks + k * 32;
#pragma unroll
        for (int c = 0; c < 32; c++) l += qr[c] * kr[c];
        float mn = fmaxf(m, l);
        float es = __expf(m - mn);
        float w  = __expf(l - mn);
        ssum = ssum * es + w;
        const float* vr = Vs + k * 32;
#pragma unroll
        for (int c = 0; c < 32; c++) acc[c] = acc[c] * es + w * vr[c];
        m = mn;
    }
    float inv = 1.0f / ssum;
#pragma unroll
    for (int c = 0; c < 32; c++) Qs[q * 33 + c] = acc[c] * inv;  // own row only
    __syncthreads();
#pragma unroll 4
    for (int idx = tid; idx < 8192; idx += 256) {
        int r = idx >> 5, c = idx & 31;
        g_wa[(size_t)(s * 256 + r) * 256 + h * 32 + c] = Qs[r * 33 + c];
    }
}

// ---------------------------------------------------------------------------
// Kernel 5: out = (sigmoid(gate_logits+gbias) * wa) @ W_o^T + M_raw + out_bias
// ---------------------------------------------------------------------------
__global__ __launch_bounds__(256) void gemm_out(
    const float* __restrict__ gbias, const float* __restrict__ Wo,
    const float* __restrict__ Mraw, const float* __restrict__ obias,
    float* __restrict__ out)
{
    __shared__ float As[64][16];
    __shared__ float Bs[64][17];
    int tid = threadIdx.x;
    int tx = tid & 15, ty = tid >> 4;
    int bm = blockIdx.y * 64, bn = blockIdx.x * 64;
    int lr = tid >> 2;
    int lc = (tid & 3) * 4;
    int r0 = bm + lr;
    const float* Brow = Wo + (size_t)(bn + lr) * 256;
    float acc[4][4] = {};
    for (int k0 = 0; k0 < 256; k0 += 16) {
        float4 w4 = *(const float4*)(g_wa + (size_t)r0 * 256 + k0 + lc);
        float4 p4 = *(const float4*)(g_proj + (size_t)r0 * EPROJ + 768 + k0 + lc);
        float4 gb = *(const float4*)(gbias + k0 + lc);
        float4 a4;
        a4.x = w4.x / (1.0f + __expf(-(p4.x + gb.x)));
        a4.y = w4.y / (1.0f + __expf(-(p4.y + gb.y)));
        a4.z = w4.z / (1.0f + __expf(-(p4.z + gb.z)));
        a4.w = w4.w / (1.0f + __expf(-(p4.w + gb.w)));
        *(float4*)&As[lr][lc] = a4;
        float4 b4 = *(const float4*)(Brow + k0 + lc);
        Bs[lr][lc] = b4.x; Bs[lr][lc + 1] = b4.y;
        Bs[lr][lc + 2] = b4.z; Bs[lr][lc + 3] = b4.w;
        __syncthreads();
#pragma unroll
        for (int kk = 0; kk < 16; kk++) {
            float a[4], b[4];
#pragma unroll
            for (int i = 0; i < 4; i++) a[i] = As[ty + 16 * i][kk];
#pragma unroll
            for (int j = 0; j < 4; j++) b[j] = Bs[tx + 16 * j][kk];
#pragma unroll
            for (int i = 0; i < 4; i++)
#pragma unroll
                for (int j = 0; j < 4; j++) acc[i][j] += a[i] * b[j];
        }
        __syncthreads();
    }
#pragma unroll
    for (int i = 0; i < 4; i++) {
        int r = bm + ty + 16 * i;
#pragma unroll
        for (int j = 0; j < 4; j++) {
            int d = bn + tx + 16 * j;
            out[(size_t)r * 256 + d] = acc[i][j] + Mraw[(size_t)r * 256 + d] + obias[d];
        }
    }
}

// ---------------------------------------------------------------------------
extern "C" void kernel_launch(void* const* d_in, const int* in_sizes, int n_in,
                              void* d_out, int out_size)
{
    const float* M_raw      = (const float*)d_in[0];
    const float* Z          = (const float*)d_in[1];
    const float* M_mask     = (const float*)d_in[2];
    const float* ln_m_scale = (const float*)d_in[3];
    const float* ln_m_bias  = (const float*)d_in[4];
    const float* ln_z_scale = (const float*)d_in[5];
    const float* ln_z_bias  = (const float*)d_in[6];
    const float* W_b        = (const float*)d_in[7];
    const float* W_qkv      = (const float*)d_in[8];
    const float* W_gate     = (const float*)d_in[9];
    const float* gbias      = (const float*)d_in[10];
    const float* W_o        = (const float*)d_in[11];
    const float* out_bias   = (const float*)d_in[12];
    float* out = (float*)d_out;

    cudaFuncSetAttribute(attn_kernel, cudaFuncAttributeMaxDynamicSharedMemorySize,
                         SMEM_ATTN);

    ln_m_kernel<<<NROWS, 256>>>(M_raw, ln_m_scale, ln_m_bias);
    pair_kernel<<<NRES * NRES, 128>>>(Z, ln_z_scale, ln_z_bias, W_b);
    gemm_proj<<<dim3(EPROJ / 64, NROWS / 64), 256>>>(W_qkv, W_gate);
    attn_kernel<<<dim3(NHEAD, NSEQ), 256, SMEM_ATTN>>>(M_mask);
    gemm_out<<<dim3(256 / 64, NROWS / 64), 256>>>(gbias, W_o, M_raw, out_bias, out);
}

// round 3
// speedup vs baseline: 1.5744x; 1.5744x over previous
#include <cuda_runtime.h>
#include <cuda_bf16.h>
#include <cstdint>
#include <math.h>

// Problem constants
#define D_NODE 256
#define D_PAIR 128
#define NHEAD  8
#define NSEQ   128
#define NRES   256
#define NROWS  (NSEQ * NRES)          // 32768
#define EPROJ  1024                    // 768 qkv + 256 gate

// Scratch
__device__ __nv_bfloat16 g_Mh[(size_t)NROWS * D_NODE];   // LN(M) hi
__device__ __nv_bfloat16 g_Ml[(size_t)NROWS * D_NODE];   // LN(M) lo
__device__ __nv_bfloat16 g_Wh[(size_t)EPROJ * D_NODE];   // [Wqkv;Wgate] hi
__device__ __nv_bfloat16 g_Wl[(size_t)EPROJ * D_NODE];   // lo
__device__ float g_proj[(size_t)NROWS * EPROJ];          // q|k|v|gate_logits
__device__ float g_pb[(size_t)NHEAD * NRES * NRES];      // pair bias [h][k][q]
__device__ float g_wa[(size_t)NROWS * D_NODE];           // attention output

__device__ __forceinline__ uint32_t smem_u32(const void* p) {
    uint32_t a;
    asm("{ .reg .u64 t; cvta.to.shared.u64 t, %1; cvt.u32.u64 %0, t; }"
        : "=r"(a) : "l"(p));
    return a;
}

#define LDM_X4(r0, r1, r2, r3, addr)                                           \
    asm volatile("ldmatrix.sync.aligned.m8n8.x4.shared.b16 {%0,%1,%2,%3}, [%4];" \
                 : "=r"(r0), "=r"(r1), "=r"(r2), "=r"(r3) : "r"(addr))

#define MMA_BF16(d, a, b0, b1)                                                 \
    asm volatile("mma.sync.aligned.m16n8k16.row.col.f32.bf16.bf16.f32 "        \
                 "{%0,%1,%2,%3}, {%4,%5,%6,%7}, {%8,%9}, {%0,%1,%2,%3};"       \
                 : "+f"((d)[0]), "+f"((d)[1]), "+f"((d)[2]), "+f"((d)[3])      \
                 : "r"((a)[0]), "r"((a)[1]), "r"((a)[2]), "r"((a)[3]),         \
                   "r"(b0), "r"(b1))

__device__ __forceinline__ float warp_sum(float v) {
#pragma unroll
    for (int o = 16; o > 0; o >>= 1) v += __shfl_xor_sync(0xffffffffu, v, o);
    return v;
}

// ---------------------------------------------------------------------------
// Kernel 1: LayerNorm over D_NODE=256 -> bf16 hi/lo split
// ---------------------------------------------------------------------------
__global__ __launch_bounds__(256) void ln_m_kernel(
    const float* __restrict__ x, const float* __restrict__ sc,
    const float* __restrict__ bi)
{
    __shared__ float red[16];
    int row = blockIdx.x;
    int tid = threadIdx.x;
    float v = x[(size_t)row * 256 + tid];
    float s1 = warp_sum(v);
    float s2 = warp_sum(v * v);
    if ((tid & 31) == 0) { red[tid >> 5] = s1; red[8 + (tid >> 5)] = s2; }
    __syncthreads();
    if (tid == 0) {
        float a = 0.f, b = 0.f;
#pragma unroll
        for (int i = 0; i < 8; i++) { a += red[i]; b += red[8 + i]; }
        red[0] = a; red[8] = b;
    }
    __syncthreads();
    float mu  = red[0] * (1.0f / 256.0f);
    float var = red[8] * (1.0f / 256.0f) - mu * mu;
    float inv = rsqrtf(var + 1e-5f);
    float y = (v - mu) * inv * sc[tid] + bi[tid];
    __nv_bfloat16 hi = __float2bfloat16(y);
    g_Mh[(size_t)row * 256 + tid] = hi;
    g_Ml[(size_t)row * 256 + tid] = __float2bfloat16(y - __bfloat162float(hi));
}

// ---------------------------------------------------------------------------
// Kernel 1b: weight conversion -> bf16 hi/lo, fused [Wqkv; Wgate]
// ---------------------------------------------------------------------------
__global__ __launch_bounds__(256) void wconv_kernel(
    const float* __restrict__ Wq, const float* __restrict__ Wg)
{
    int i = blockIdx.x * 256 + threadIdx.x;          // 0 .. 1024*256-1
    float v = (i < 768 * 256) ? Wq[i] : Wg[i - 768 * 256];
    __nv_bfloat16 hi = __float2bfloat16(v);
    g_Wh[i] = hi;
    g_Wl[i] = __float2bfloat16(v - __bfloat162float(hi));
}

// ---------------------------------------------------------------------------
// Kernel 2: LN(Z) + pair bias -> pb[h][k][q]
// ---------------------------------------------------------------------------
__global__ __launch_bounds__(128) void pair_kernel(
    const float* __restrict__ Z, const float* __restrict__ sc,
    const float* __restrict__ bi, const float* __restrict__ Wb)
{
    __shared__ float red[8];
    __shared__ float zn[128];
    int bid = blockIdx.x;          // = q*256 + k
    int q = bid >> 8, k = bid & 255;
    int tid = threadIdx.x;
    float v = Z[(size_t)bid * 128 + tid];
    float s1 = warp_sum(v);
    float s2 = warp_sum(v * v);
    if ((tid & 31) == 0) { red[tid >> 5] = s1; red[4 + (tid >> 5)] = s2; }
    __syncthreads();
    if (tid == 0) {
        float a = 0.f, b = 0.f;
#pragma unroll
        for (int i = 0; i < 4; i++) { a += red[i]; b += red[4 + i]; }
        red[0] = a; red[4] = b;
    }
    __syncthreads();
    float mu  = red[0] * (1.0f / 128.0f);
    float var = red[4] * (1.0f / 128.0f) - mu * mu;
    zn[tid] = (v - mu) * rsqrtf(var + 1e-5f) * sc[tid] + bi[tid];
    __syncthreads();
    int w = tid >> 5, l = tid & 31;
#pragma unroll
    for (int j = 0; j < 2; j++) {
        int h = w * 2 + j;
        const float* wb = Wb + h * 128;
        float p = zn[l] * wb[l] + zn[l + 32] * wb[l + 32]
                + zn[l + 64] * wb[l + 64] + zn[l + 96] * wb[l + 96];
        p = warp_sum(p);
        if (l == 0) g_pb[(size_t)(h * 256 + k) * 256 + q] = p;
    }
}

// ---------------------------------------------------------------------------
// Kernel 3: projection GEMM via mma.sync bf16, hi/lo split (3x MMA).
// BM=128 BN=128 BK=32; 8 warps, each 64x32 warp tile.
// smem rows padded to 80B -> conflict-free ldmatrix.
// ---------------------------------------------------------------------------
#define OFF_AH 0
#define OFF_AL 10240
#define OFF_BH 20480
#define OFF_BL 30720

__global__ __launch_bounds__(256) void gemm_proj_mma()
{
    __shared__ __align__(16) unsigned char smb[40960];
    uint32_t sb = smem_u32(smb);
    int tid = threadIdx.x;
    int lane = tid & 31, wid = tid >> 5;
    int wm = wid >> 2, wn = wid & 3;           // 2 x 4 warp grid
    int bm = blockIdx.y * 128, bn = blockIdx.x * 128;

    float acc[4][4][4] = {};

    int lrow = tid >> 1, lhalf = tid & 1;      // 128 rows x 2 halves of 16 bf16
    size_t gA = (size_t)(bm + lrow) * 256 + lhalf * 16;
    size_t gB = (size_t)(bn + lrow) * 256 + lhalf * 16;
    uint32_t sOff = lrow * 80 + lhalf * 32;

    // ldmatrix lane addressing (within-tile)
    uint32_t aRow = (lane & 15);
    uint32_t aChunk = (lane >> 4) << 3;        // 0 or 8 (k offset)
    uint32_t bRow = (lane & 7) + ((lane >> 4) << 3);   // n row within 16
    uint32_t bChunk = ((lane >> 3) & 1) << 3;  // 0 or 8 (k offset)

    for (int k0 = 0; k0 < 256; k0 += 32) {
        if (k0) __syncthreads();
        // stage A hi/lo and B hi/lo tiles (each 128 rows x 32 bf16)
        {
            const uint4* p;
            p = (const uint4*)(g_Mh + gA + k0);
            *(uint4*)(smb + OFF_AH + sOff) = p[0];
            *(uint4*)(smb + OFF_AH + sOff + 16) = p[1];
            p = (const uint4*)(g_Ml + gA + k0);
            *(uint4*)(smb + OFF_AL + sOff) = p[0];
            *(uint4*)(smb + OFF_AL + sOff + 16) = p[1];
            p = (const uint4*)(g_Wh + gB + k0);
            *(uint4*)(smb + OFF_BH + sOff) = p[0];
            *(uint4*)(smb + OFF_BH + sOff + 16) = p[1];
            p = (const uint4*)(g_Wl + gB + k0);
            *(uint4*)(smb + OFF_BL + sOff) = p[0];
            *(uint4*)(smb + OFF_BL + sOff + 16) = p[1];
        }
        __syncthreads();

#pragma unroll
        for (int ks = 0; ks < 2; ks++) {
            uint32_t ah[4][4], al[4][4], bh[2][4], bl[2][4];
#pragma unroll
            for (int mi = 0; mi < 4; mi++) {
                uint32_t ad = sb + (wm * 64 + mi * 16 + aRow) * 80
                            + (ks * 16 + aChunk) * 2;
                LDM_X4(ah[mi][0], ah[mi][1], ah[mi][2], ah[mi][3], ad + OFF_AH);
                LDM_X4(al[mi][0], al[mi][1], al[mi][2], al[mi][3], ad + OFF_AL);
            }
#pragma unroll
            for (int ng = 0; ng < 2; ng++) {
                uint32_t bd = sb + (wn * 32 + ng * 16 + bRow) * 80
                            + (ks * 16 + bChunk) * 2;
                LDM_X4(bh[ng][0], bh[ng][1], bh[ng][2], bh[ng][3], bd + OFF_BH);
                LDM_X4(bl[ng][0], bl[ng][1], bl[ng][2], bl[ng][3], bd + OFF_BL);
            }
#pragma unroll
            for (int mi = 0; mi < 4; mi++) {
#pragma unroll
                for (int nj = 0; nj < 4; nj++) {
                    int ng = nj >> 1, sub = (nj & 1) * 2;
                    MMA_BF16(acc[mi][nj], ah[mi], bh[ng][sub], bh[ng][sub + 1]);
                    MMA_BF16(acc[mi][nj], ah[mi], bl[ng][sub], bl[ng][sub + 1]);
                    MMA_BF16(acc[mi][nj], al[mi], bh[ng][sub], bh[ng][sub + 1]);
                }
            }
        }
    }

    // epilogue: d-frag lane mapping: rows l/4 and l/4+8, cols (l%4)*2..+1
    int r0 = bm + wm * 64 + (lane >> 2);
    int c0 = bn + wn * 32 + (lane & 3) * 2;
#pragma unroll
    for (int mi = 0; mi < 4; mi++) {
#pragma unroll
        for (int nj = 0; nj < 4; nj++) {
            float* d = g_proj + (size_t)(r0 + mi * 16) * EPROJ + c0 + nj * 8;
            *(float2*)d = make_float2(acc[mi][nj][0], acc[mi][nj][1]);
            *(float2*)(d + 8 * EPROJ) = make_float2(acc[mi][nj][2], acc[mi][nj][3]);
        }
    }
}

// ---------------------------------------------------------------------------
// Kernel 4: attention. block=(h,s), 256 threads; thread owns one q-row.
// k tiled by 8: batched pb loads, float4 K/V, one rescale per tile.
// ---------------------------------------------------------------------------
#define SMEM_ATTN ((8192 + 8192 + 256 * 33 + 256) * 4)

__global__ __launch_bounds__(256) void attn_kernel(const float* __restrict__ mask)
{
    extern __shared__ float sm[];
    float* Ks = sm;                 // [256][32]
    float* Vs = sm + 8192;          // [256][32]
    float* Qs = sm + 16384;         // [256][33] padded
    float* mb = sm + 16384 + 256 * 33;
    int h = blockIdx.x, s = blockIdx.y;
    int tid = threadIdx.x;
    const float* base = g_proj + (size_t)s * 256 * EPROJ;
#pragma unroll 4
    for (int idx = tid; idx < 8192; idx += 256) {
        int r = idx >> 5, c = idx & 31;
        int ro = r * EPROJ + h * 32 + c;
        Qs[r * 33 + c] = base[ro];
        Ks[idx]        = base[ro + 256];
        Vs[idx]        = base[ro + 512];
    }
    mb[tid] = 1e9f * (mask[s * 256 + tid] - 1.0f);
    __syncthreads();

    int q = tid;
    float qr[32];
    const float scale = 0.17677669529663688f;   // 1/sqrt(32)
#pragma unroll
    for (int c = 0; c < 32; c++) qr[c] = Qs[q * 33 + c] * scale;

    float m = -1e30f, ssum = 0.f;
    float acc[32] = {};
    const float* pbh = g_pb + (size_t)h * 65536 + q;
#pragma unroll 1
    for (int k0 = 0; k0 < 256; k0 += 8) {
        float lg[8];
#pragma unroll
        for (int j = 0; j < 8; j++) lg[j] = mb[k0 + j] + pbh[(size_t)(k0 + j) * 256];
#pragma unroll
        for (int j = 0; j < 8; j++) {
            const float4* kr = (const float4*)(Ks + (k0 + j) * 32);
            float d0 = 0.f, d1 = 0.f, d2 = 0.f, d3 = 0.f;
#pragma unroll
            for (int i = 0; i < 8; i++) {
                float4 kv = kr[i];
                d0 += qr[4 * i] * kv.x; d1 += qr[4 * i + 1] * kv.y;
                d2 += qr[4 * i + 2] * kv.z; d3 += qr[4 * i + 3] * kv.w;
            }
            lg[j] += (d0 + d1) + (d2 + d3);
        }
        float tm = m;
#pragma unroll
        for (int j = 0; j < 8; j++) tm = fmaxf(tm, lg[j]);
        float es = __expf(m - tm);
        m = tm;
        ssum *= es;
#pragma unroll
        for (int c = 0; c < 32; c++) acc[c] *= es;
#pragma unroll
        for (int j = 0; j < 8; j++) {
            float w = __expf(lg[j] - m);
            ssum += w;
            const float4* vr = (const float4*)(Vs + (k0 + j) * 32);
#pragma unroll
            for (int i = 0; i < 8; i++) {
                float4 vv = vr[i];
                acc[4 * i]     += w * vv.x; acc[4 * i + 1] += w * vv.y;
                acc[4 * i + 2] += w * vv.z; acc[4 * i + 3] += w * vv.w;
            }
        }
    }
    float inv = 1.0f / ssum;
#pragma unroll
    for (int c = 0; c < 32; c++) Qs[q * 33 + c] = acc[c] * inv;
    __syncthreads();
#pragma unroll 4
    for (int idx = tid; idx < 8192; idx += 256) {
        int r = idx >> 5, c = idx & 31;
        g_wa[(size_t)(s * 256 + r) * 256 + h * 32 + c] = Qs[r * 33 + c];
    }
}

// ---------------------------------------------------------------------------
// Kernel 5: out = (sigmoid(gate)*wa) @ W_o^T + M_raw + out_bias (fp32)
// ---------------------------------------------------------------------------
__global__ __launch_bounds__(256) void gemm_out(
    const float* __restrict__ gbias, const float* __restrict__ Wo,
    const float* __restrict__ Mraw, const float* __restrict__ obias,
    float* __restrict__ out)
{
    __shared__ float As[64][16];
    __shared__ float Bs[64][17];
    int tid = threadIdx.x;
    int tx = tid & 15, ty = tid >> 4;
    int bm = blockIdx.y * 64, bn = blockIdx.x * 64;
    int lr = tid >> 2;
    int lc = (tid & 3) * 4;
    int r0 = bm + lr;
    const float* Brow = Wo + (size_t)(bn + lr) * 256;
    float acc[4][4] = {};
    for (int k0 = 0; k0 < 256; k0 += 16) {
        float4 w4 = *(const float4*)(g_wa + (size_t)r0 * 256 + k0 + lc);
        float4 p4 = *(const float4*)(g_proj + (size_t)r0 * EPROJ + 768 + k0 + lc);
        float4 gb = *(const float4*)(gbias + k0 + lc);
        float4 a4;
        a4.x = w4.x / (1.0f + __expf(-(p4.x + gb.x)));
        a4.y = w4.y / (1.0f + __expf(-(p4.y + gb.y)));
        a4.z = w4.z / (1.0f + __expf(-(p4.z + gb.z)));
        a4.w = w4.w / (1.0f + __expf(-(p4.w + gb.w)));
        *(float4*)&As[lr][lc] = a4;
        float4 b4 = *(const float4*)(Brow + k0 + lc);
        Bs[lr][lc] = b4.x; Bs[lr][lc + 1] = b4.y;
        Bs[lr][lc + 2] = b4.z; Bs[lr][lc + 3] = b4.w;
        __syncthreads();
#pragma unroll
        for (int kk = 0; kk < 16; kk++) {
            float a[4], b[4];
#pragma unroll
            for (int i = 0; i < 4; i++) a[i] = As[ty + 16 * i][kk];
#pragma unroll
            for (int j = 0; j < 4; j++) b[j] = Bs[tx + 16 * j][kk];
#pragma unroll
            for (int i = 0; i < 4; i++)
#pragma unroll
                for (int j = 0; j < 4; j++) acc[i][j] += a[i] * b[j];
        }
        __syncthreads();
    }
#pragma unroll
    for (int i = 0; i < 4; i++) {
        int r = bm + ty + 16 * i;
#pragma unroll
        for (int j = 0; j < 4; j++) {
            int d = bn + tx + 16 * j;
            out[(size_t)r * 256 + d] = acc[i][j] + Mraw[(size_t)r * 256 + d] + obias[d];
        }
    }
}

// ---------------------------------------------------------------------------
extern "C" void kernel_launch(void* const* d_in, const int* in_sizes, int n_in,
                              void* d_out, int out_size)
{
    const float* M_raw      = (const float*)d_in[0];
    const float* Z          = (const float*)d_in[1];
    const float* M_mask     = (const float*)d_in[2];
    const float* ln_m_scale = (const float*)d_in[3];
    const float* ln_m_bias  = (const float*)d_in[4];
    const float* ln_z_scale = (const float*)d_in[5];
    const float* ln_z_bias  = (const float*)d_in[6];
    const float* W_b        = (const float*)d_in[7];
    const float* W_qkv      = (const float*)d_in[8];
    const float* W_gate     = (const float*)d_in[9];
    const float* gbias      = (const float*)d_in[10];
    const float* W_o        = (const float*)d_in[11];
    const float* out_bias   = (const float*)d_in[12];
    float* out = (float*)d_out;

    cudaFuncSetAttribute(attn_kernel, cudaFuncAttributeMaxDynamicSharedMemorySize,
                         SMEM_ATTN);

    ln_m_kernel<<<NROWS, 256>>>(M_raw, ln_m_scale, ln_m_bias);
    wconv_kernel<<<EPROJ, 256>>>(W_qkv, W_gate);
    pair_kernel<<<NRES * NRES, 128>>>(Z, ln_z_scale, ln_z_bias, W_b);
    gemm_proj_mma<<<dim3(EPROJ / 128, NROWS / 128), 256>>>();
    attn_kernel<<<dim3(NHEAD, NSEQ), 256, SMEM_ATTN>>>(M_mask);
    gemm_out<<<dim3(256 / 64, NROWS / 64), 256>>>(gbias, W_o, M_raw, out_bias, out);
}

// round 4
// speedup vs baseline: 1.7500x; 1.1115x over previous
#include <cuda_runtime.h>
#include <cuda_bf16.h>
#include <cstdint>
#include <math.h>

// Problem constants
#define D_NODE 256
#define D_PAIR 128
#define NHEAD  8
#define NSEQ   128
#define NRES   256
#define NROWS  (NSEQ * NRES)          // 32768
#define EPROJ  1024                    // 768 qkv + 256 gate

// Scratch
__device__ __nv_bfloat16 g_Mh[(size_t)NROWS * D_NODE];   // LN(M) hi
__device__ __nv_bfloat16 g_Ml[(size_t)NROWS * D_NODE];   // LN(M) lo
__device__ __nv_bfloat16 g_Wh[(size_t)EPROJ * D_NODE];   // [Wqkv;Wgate] hi
__device__ __nv_bfloat16 g_Wl[(size_t)EPROJ * D_NODE];   // lo
__device__ __nv_bfloat16 g_Oh[(size_t)D_NODE * D_NODE];  // W_o hi
__device__ __nv_bfloat16 g_Ol[(size_t)D_NODE * D_NODE];  // W_o lo
__device__ float g_proj[(size_t)NROWS * EPROJ];          // q|k|v|gate_logits
__device__ float g_pb[(size_t)NHEAD * NRES * NRES];      // pair bias [h][k][q]
__device__ float g_wa[(size_t)NROWS * D_NODE];           // attention output

__device__ __forceinline__ uint32_t smem_u32(const void* p) {
    uint32_t a;
    asm("{ .reg .u64 t; cvta.to.shared.u64 t, %1; cvt.u32.u64 %0, t; }"
        : "=r"(a) : "l"(p));
    return a;
}

#define LDM_X4(r0, r1, r2, r3, addr)                                           \
    asm volatile("ldmatrix.sync.aligned.m8n8.x4.shared.b16 {%0,%1,%2,%3}, [%4];" \
                 : "=r"(r0), "=r"(r1), "=r"(r2), "=r"(r3) : "r"(addr))

#define MMA_BF16(d, a, b0, b1)                                                 \
    asm volatile("mma.sync.aligned.m16n8k16.row.col.f32.bf16.bf16.f32 "        \
                 "{%0,%1,%2,%3}, {%4,%5,%6,%7}, {%8,%9}, {%0,%1,%2,%3};"       \
                 : "+f"((d)[0]), "+f"((d)[1]), "+f"((d)[2]), "+f"((d)[3])      \
                 : "r"((a)[0]), "r"((a)[1]), "r"((a)[2]), "r"((a)[3]),         \
                   "r"(b0), "r"(b1))

#define CP16(s, g)                                                             \
    asm volatile("cp.async.cg.shared.global [%0], [%1], 16;" :: "r"(s), "l"(g))
#define CP_COMMIT() asm volatile("cp.async.commit_group;" ::: "memory")

__device__ __forceinline__ float warp_sum(float v) {
#pragma unroll
    for (int o = 16; o > 0; o >>= 1) v += __shfl_xor_sync(0xffffffffu, v, o);
    return v;
}

// ---------------------------------------------------------------------------
// Kernel 1: LayerNorm over D_NODE=256 -> bf16 hi/lo split
// ---------------------------------------------------------------------------
__global__ __launch_bounds__(256) void ln_m_kernel(
    const float* __restrict__ x, const float* __restrict__ sc,
    const float* __restrict__ bi)
{
    __shared__ float red[16];
    int row = blockIdx.x;
    int tid = threadIdx.x;
    float v = x[(size_t)row * 256 + tid];
    float s1 = warp_sum(v);
    float s2 = warp_sum(v * v);
    if ((tid & 31) == 0) { red[tid >> 5] = s1; red[8 + (tid >> 5)] = s2; }
    __syncthreads();
    if (tid == 0) {
        float a = 0.f, b = 0.f;
#pragma unroll
        for (int i = 0; i < 8; i++) { a += red[i]; b += red[8 + i]; }
        red[0] = a; red[8] = b;
    }
    __syncthreads();
    float mu  = red[0] * (1.0f / 256.0f);
    float var = red[8] * (1.0f / 256.0f) - mu * mu;
    float inv = rsqrtf(var + 1e-5f);
    float y = (v - mu) * inv * sc[tid] + bi[tid];
    __nv_bfloat16 hi = __float2bfloat16(y);
    g_Mh[(size_t)row * 256 + tid] = hi;
    g_Ml[(size_t)row * 256 + tid] = __float2bfloat16(y - __bfloat162float(hi));
}

// ---------------------------------------------------------------------------
// Kernel 1b/1c: weight conversion -> bf16 hi/lo
// ---------------------------------------------------------------------------
__global__ __launch_bounds__(256) void wconv_kernel(
    const float* __restrict__ Wq, const float* __restrict__ Wg)
{
    int i = blockIdx.x * 256 + threadIdx.x;          // 0 .. 1024*256-1
    float v = (i < 768 * 256) ? Wq[i] : Wg[i - 768 * 256];
    __nv_bfloat16 hi = __float2bfloat16(v);
    g_Wh[i] = hi;
    g_Wl[i] = __float2bfloat16(v - __bfloat162float(hi));
}

__global__ __launch_bounds__(256) void wconv_o_kernel(const float* __restrict__ Wo)
{
    int i = blockIdx.x * 256 + threadIdx.x;          // 0 .. 256*256-1
    float v = Wo[i];
    __nv_bfloat16 hi = __float2bfloat16(v);
    g_Oh[i] = hi;
    g_Ol[i] = __float2bfloat16(v - __bfloat162float(hi));
}

// ---------------------------------------------------------------------------
// Kernel 2: LN(Z) + pair bias -> pb[h][k][q]
// ---------------------------------------------------------------------------
__global__ __launch_bounds__(128) void pair_kernel(
    const float* __restrict__ Z, const float* __restrict__ sc,
    const float* __restrict__ bi, const float* __restrict__ Wb)
{
    __shared__ float red[8];
    __shared__ float zn[128];
    int bid = blockIdx.x;          // = q*256 + k
    int q = bid >> 8, k = bid & 255;
    int tid = threadIdx.x;
    float v = Z[(size_t)bid * 128 + tid];
    float s1 = warp_sum(v);
    float s2 = warp_sum(v * v);
    if ((tid & 31) == 0) { red[tid >> 5] = s1; red[4 + (tid >> 5)] = s2; }
    __syncthreads();
    if (tid == 0) {
        float a = 0.f, b = 0.f;
#pragma unroll
        for (int i = 0; i < 4; i++) { a += red[i]; b += red[4 + i]; }
        red[0] = a; red[4] = b;
    }
    __syncthreads();
    float mu  = red[0] * (1.0f / 128.0f);
    float var = red[4] * (1.0f / 128.0f) - mu * mu;
    zn[tid] = (v - mu) * rsqrtf(var + 1e-5f) * sc[tid] + bi[tid];
    __syncthreads();
    int w = tid >> 5, l = tid & 31;
#pragma unroll
    for (int j = 0; j < 2; j++) {
        int h = w * 2 + j;
        const float* wb = Wb + h * 128;
        float p = zn[l] * wb[l] + zn[l + 32] * wb[l + 32]
                + zn[l + 64] * wb[l + 64] + zn[l + 96] * wb[l + 96];
        p = warp_sum(p);
        if (l == 0) g_pb[(size_t)(h * 256 + k) * 256 + q] = p;
    }
}

// ---------------------------------------------------------------------------
// Kernel 3: projection GEMM via mma.sync bf16 hi/lo, cp.async 2-stage pipeline
// BM=128 BN=128 BK=32; 8 warps, each 64x32 warp tile; rows padded to 80B.
// ---------------------------------------------------------------------------
#define OFF_AH 0
#define OFF_AL 10240
#define OFF_BH 20480
#define OFF_BL 30720
#define PROJ_STAGE 40960
#define PROJ_SMEM  (2 * PROJ_STAGE)

__global__ __launch_bounds__(256) void gemm_proj_mma()
{
    extern __shared__ __align__(16) unsigned char smb[];
    uint32_t sbase = smem_u32(smb);
    int tid = threadIdx.x;
    int lane = tid & 31, wid = tid >> 5;
    int wm = wid >> 2, wn = wid & 3;           // 2 x 4 warp grid
    int bm = blockIdx.y * 128, bn = blockIdx.x * 128;

    float acc[4][4][4] = {};

    int lrow = tid >> 1, lhalf = tid & 1;      // 128 rows x 2 halves of 16 bf16
    size_t gA = (size_t)(bm + lrow) * 256 + lhalf * 16;
    size_t gB = (size_t)(bn + lrow) * 256 + lhalf * 16;
    uint32_t sOff = lrow * 80 + lhalf * 32;

    uint32_t aRow = (lane & 15);
    uint32_t aChunk = (lane >> 4) << 3;
    uint32_t bRow = (lane & 7) + ((lane >> 4) << 3);
    uint32_t bChunk = ((lane >> 3) & 1) << 3;

    // prologue: stage tile 0 into buf 0
    {
        uint32_t b = sbase;
        CP16(b + OFF_AH + sOff, g_Mh + gA); CP16(b + OFF_AH + sOff + 16, g_Mh + gA + 8);
        CP16(b + OFF_AL + sOff, g_Ml + gA); CP16(b + OFF_AL + sOff + 16, g_Ml + gA + 8);
        CP16(b + OFF_BH + sOff, g_Wh + gB); CP16(b + OFF_BH + sOff + 16, g_Wh + gB + 8);
        CP16(b + OFF_BL + sOff, g_Wl + gB); CP16(b + OFF_BL + sOff + 16, g_Wl + gB + 8);
        CP_COMMIT();
    }

#pragma unroll 1
    for (int t = 0; t < 8; t++) {
        if (t < 7) {
            int c = t + 1;
            uint32_t b = sbase + (c & 1) * PROJ_STAGE;
            const __nv_bfloat16* p;
            p = g_Mh + gA + c * 32;
            CP16(b + OFF_AH + sOff, p); CP16(b + OFF_AH + sOff + 16, p + 8);
            p = g_Ml + gA + c * 32;
            CP16(b + OFF_AL + sOff, p); CP16(b + OFF_AL + sOff + 16, p + 8);
            p = g_Wh + gB + c * 32;
            CP16(b + OFF_BH + sOff, p); CP16(b + OFF_BH + sOff + 16, p + 8);
            p = g_Wl + gB + c * 32;
            CP16(b + OFF_BL + sOff, p); CP16(b + OFF_BL + sOff + 16, p + 8);
            CP_COMMIT();
            asm volatile("cp.async.wait_group 1;" ::: "memory");
        } else {
            asm volatile("cp.async.wait_group 0;" ::: "memory");
        }
        __syncthreads();

        uint32_t sb = sbase + (t & 1) * PROJ_STAGE;
#pragma unroll
        for (int ks = 0; ks < 2; ks++) {
            uint32_t ah[4][4], al[4][4], bh[2][4], bl[2][4];
#pragma unroll
            for (int mi = 0; mi < 4; mi++) {
                uint32_t ad = sb + (wm * 64 + mi * 16 + aRow) * 80
                            + (ks * 16 + aChunk) * 2;
                LDM_X4(ah[mi][0], ah[mi][1], ah[mi][2], ah[mi][3], ad + OFF_AH);
                LDM_X4(al[mi][0], al[mi][1], al[mi][2], al[mi][3], ad + OFF_AL);
            }
#pragma unroll
            for (int ng = 0; ng < 2; ng++) {
                uint32_t bd = sb + (wn * 32 + ng * 16 + bRow) * 80
                            + (ks * 16 + bChunk) * 2;
                LDM_X4(bh[ng][0], bh[ng][1], bh[ng][2], bh[ng][3], bd + OFF_BH);
                LDM_X4(bl[ng][0], bl[ng][1], bl[ng][2], bl[ng][3], bd + OFF_BL);
            }
#pragma unroll
            for (int mi = 0; mi < 4; mi++) {
#pragma unroll
                for (int nj = 0; nj < 4; nj++) {
                    int ng = nj >> 1, sub = (nj & 1) * 2;
                    MMA_BF16(acc[mi][nj], ah[mi], bh[ng][sub], bh[ng][sub + 1]);
                    MMA_BF16(acc[mi][nj], ah[mi], bl[ng][sub], bl[ng][sub + 1]);
                    MMA_BF16(acc[mi][nj], al[mi], bh[ng][sub], bh[ng][sub + 1]);
                }
            }
        }
        __syncthreads();
    }

    int r0 = bm + wm * 64 + (lane >> 2);
    int c0 = bn + wn * 32 + (lane & 3) * 2;
#pragma unroll
    for (int mi = 0; mi < 4; mi++) {
#pragma unroll
        for (int nj = 0; nj < 4; nj++) {
            float* d = g_proj + (size_t)(r0 + mi * 16) * EPROJ + c0 + nj * 8;
            *(float2*)d = make_float2(acc[mi][nj][0], acc[mi][nj][1]);
            *(float2*)(d + 8 * EPROJ) = make_float2(acc[mi][nj][2], acc[mi][nj][3]);
        }
    }
}

// ---------------------------------------------------------------------------
// Kernel 4: attention. block=(h,s), 256 threads; thread owns one q-row.
// ---------------------------------------------------------------------------
#define SMEM_ATTN ((8192 + 8192 + 256 * 33 + 256) * 4)

__global__ __launch_bounds__(256) void attn_kernel(const float* __restrict__ mask)
{
    extern __shared__ float sm[];
    float* Ks = sm;
    float* Vs = sm + 8192;
    float* Qs = sm + 16384;
    float* mb = sm + 16384 + 256 * 33;
    int h = blockIdx.x, s = blockIdx.y;
    int tid = threadIdx.x;
    const float* base = g_proj + (size_t)s * 256 * EPROJ;
#pragma unroll 4
    for (int idx = tid; idx < 8192; idx += 256) {
        int r = idx >> 5, c = idx & 31;
        int ro = r * EPROJ + h * 32 + c;
        Qs[r * 33 + c] = base[ro];
        Ks[idx]        = base[ro + 256];
        Vs[idx]        = base[ro + 512];
    }
    mb[tid] = 1e9f * (mask[s * 256 + tid] - 1.0f);
    __syncthreads();

    int q = tid;
    float qr[32];
    const float scale = 0.17677669529663688f;
#pragma unroll
    for (int c = 0; c < 32; c++) qr[c] = Qs[q * 33 + c] * scale;

    float m = -1e30f, ssum = 0.f;
    float acc[32] = {};
    const float* pbh = g_pb + (size_t)h * 65536 + q;
#pragma unroll 1
    for (int k0 = 0; k0 < 256; k0 += 8) {
        float lg[8];
#pragma unroll
        for (int j = 0; j < 8; j++) lg[j] = mb[k0 + j] + pbh[(size_t)(k0 + j) * 256];
#pragma unroll
        for (int j = 0; j < 8; j++) {
            const float4* kr = (const float4*)(Ks + (k0 + j) * 32);
            float d0 = 0.f, d1 = 0.f, d2 = 0.f, d3 = 0.f;
#pragma unroll
            for (int i = 0; i < 8; i++) {
                float4 kv = kr[i];
                d0 += qr[4 * i] * kv.x; d1 += qr[4 * i + 1] * kv.y;
                d2 += qr[4 * i + 2] * kv.z; d3 += qr[4 * i + 3] * kv.w;
            }
            lg[j] += (d0 + d1) + (d2 + d3);
        }
        float tm = m;
#pragma unroll
        for (int j = 0; j < 8; j++) tm = fmaxf(tm, lg[j]);
        float es = __expf(m - tm);
        m = tm;
        ssum *= es;
#pragma unroll
        for (int c = 0; c < 32; c++) acc[c] *= es;
#pragma unroll
        for (int j = 0; j < 8; j++) {
            float w = __expf(lg[j] - m);
            ssum += w;
            const float4* vr = (const float4*)(Vs + (k0 + j) * 32);
#pragma unroll
            for (int i = 0; i < 8; i++) {
                float4 vv = vr[i];
                acc[4 * i]     += w * vv.x; acc[4 * i + 1] += w * vv.y;
                acc[4 * i + 2] += w * vv.z; acc[4 * i + 3] += w * vv.w;
            }
        }
    }
    float inv = 1.0f / ssum;
#pragma unroll
    for (int c = 0; c < 32; c++) Qs[q * 33 + c] = acc[c] * inv;
    __syncthreads();
#pragma unroll 4
    for (int idx = tid; idx < 8192; idx += 256) {
        int r = idx >> 5, c = idx & 31;
        g_wa[(size_t)(s * 256 + r) * 256 + h * 32 + c] = Qs[r * 33 + c];
    }
}

// ---------------------------------------------------------------------------
// Kernel 5: out = (sigmoid(gate)*wa) @ W_o^T + M_raw + out_bias
// mma.sync bf16 hi/lo; gate+split fused into A staging.
// BM=128 BN=128 BK=32; 8 warps.
// ---------------------------------------------------------------------------
__global__ __launch_bounds__(256) void gemm_out_mma(
    const float* __restrict__ gbias, const float* __restrict__ Mraw,
    const float* __restrict__ obias, float* __restrict__ out)
{
    __shared__ __align__(16) unsigned char smb[40960];
    uint32_t sb = smem_u32(smb);
    int tid = threadIdx.x;
    int lane = tid & 31, wid = tid >> 5;
    int wm = wid >> 2, wn = wid & 3;
    int bm = blockIdx.y * 128, bn = blockIdx.x * 128;

    float acc[4][4][4] = {};

    int lrow = tid >> 1, lhalf = tid & 1;
    uint32_t sOff = lrow * 80 + lhalf * 32;
    size_t rA = (size_t)(bm + lrow);
    size_t gB = (size_t)(bn + lrow) * 256 + lhalf * 16;

    uint32_t aRow = (lane & 15);
    uint32_t aChunk = (lane >> 4) << 3;
    uint32_t bRow = (lane & 7) + ((lane >> 4) << 3);
    uint32_t bChunk = ((lane >> 3) & 1) << 3;

#pragma unroll 1
    for (int t = 0; t < 8; t++) {
        int k0 = t * 32 + lhalf * 16;
        if (t) __syncthreads();
        // A staging: a = sigmoid(gate_logit + gbias) * wa, split hi/lo
        {
            __align__(16) __nv_bfloat16 hi[16], lo[16];
            const float* wp = g_wa + rA * 256 + k0;
            const float* pp = g_proj + rA * EPROJ + 768 + k0;
            const float* gp = gbias + k0;
#pragma unroll
            for (int i = 0; i < 4; i++) {
                float4 w4 = *(const float4*)(wp + i * 4);
                float4 p4 = *(const float4*)(pp + i * 4);
                float4 g4 = *(const float4*)(gp + i * 4);
                float a0 = w4.x / (1.0f + __expf(-(p4.x + g4.x)));
                float a1 = w4.y / (1.0f + __expf(-(p4.y + g4.y)));
                float a2 = w4.z / (1.0f + __expf(-(p4.z + g4.z)));
                float a3 = w4.w / (1.0f + __expf(-(p4.w + g4.w)));
                __nv_bfloat16 h0 = __float2bfloat16(a0);
                __nv_bfloat16 h1 = __float2bfloat16(a1);
                __nv_bfloat16 h2 = __float2bfloat16(a2);
                __nv_bfloat16 h3 = __float2bfloat16(a3);
                hi[i * 4] = h0; hi[i * 4 + 1] = h1; hi[i * 4 + 2] = h2; hi[i * 4 + 3] = h3;
                lo[i * 4]     = __float2bfloat16(a0 - __bfloat162float(h0));
                lo[i * 4 + 1] = __float2bfloat16(a1 - __bfloat162float(h1));
                lo[i * 4 + 2] = __float2bfloat16(a2 - __bfloat162float(h2));
                lo[i * 4 + 3] = __float2bfloat16(a3 - __bfloat162float(h3));
            }
            *(uint4*)(smb + OFF_AH + sOff)      = *(uint4*)hi;
            *(uint4*)(smb + OFF_AH + sOff + 16) = *(uint4*)(hi + 8);
            *(uint4*)(smb + OFF_AL + sOff)      = *(uint4*)lo;
            *(uint4*)(smb + OFF_AL + sOff + 16) = *(uint4*)(lo + 8);
        }
        // B staging: W_o hi/lo
        {
            const __nv_bfloat16* p = g_Oh + gB + t * 32;
            *(uint4*)(smb + OFF_BH + sOff)      = *(const uint4*)p;
            *(uint4*)(smb + OFF_BH + sOff + 16) = *(const uint4*)(p + 8);
            p = g_Ol + gB + t * 32;
            *(uint4*)(smb + OFF_BL + sOff)      = *(const uint4*)p;
            *(uint4*)(smb + OFF_BL + sOff + 16) = *(const uint4*)(p + 8);
        }
        __syncthreads();

#pragma unroll
        for (int ks = 0; ks < 2; ks++) {
            uint32_t ah[4][4], al[4][4], bh[2][4], bl[2][4];
#pragma unroll
            for (int mi = 0; mi < 4; mi++) {
                uint32_t ad = sb + (wm * 64 + mi * 16 + aRow) * 80
                            + (ks * 16 + aChunk) * 2;
                LDM_X4(ah[mi][0], ah[mi][1], ah[mi][2], ah[mi][3], ad + OFF_AH);
                LDM_X4(al[mi][0], al[mi][1], al[mi][2], al[mi][3], ad + OFF_AL);
            }
#pragma unroll
            for (int ng = 0; ng < 2; ng++) {
                uint32_t bd = sb + (wn * 32 + ng * 16 + bRow) * 80
                            + (ks * 16 + bChunk) * 2;
                LDM_X4(bh[ng][0], bh[ng][1], bh[ng][2], bh[ng][3], bd + OFF_BH);
                LDM_X4(bl[ng][0], bl[ng][1], bl[ng][2], bl[ng][3], bd + OFF_BL);
            }
#pragma unroll
            for (int mi = 0; mi < 4; mi++) {
#pragma unroll
                for (int nj = 0; nj < 4; nj++) {
                    int ng = nj >> 1, sub = (nj & 1) * 2;
                    MMA_BF16(acc[mi][nj], ah[mi], bh[ng][sub], bh[ng][sub + 1]);
                    MMA_BF16(acc[mi][nj], ah[mi], bl[ng][sub], bl[ng][sub + 1]);
                    MMA_BF16(acc[mi][nj], al[mi], bh[ng][sub], bh[ng][sub + 1]);
                }
            }
        }
    }

    int r0 = bm + wm * 64 + (lane >> 2);
    int c0 = bn + wn * 32 + (lane & 3) * 2;
#pragma unroll
    for (int mi = 0; mi < 4; mi++) {
#pragma unroll
        for (int nj = 0; nj < 4; nj++) {
            int r = r0 + mi * 16, c = c0 + nj * 8;
            float ob0 = obias[c], ob1 = obias[c + 1];
            float2 m0 = *(const float2*)(Mraw + (size_t)r * 256 + c);
            *(float2*)(out + (size_t)r * 256 + c) =
                make_float2(acc[mi][nj][0] + m0.x + ob0, acc[mi][nj][1] + m0.y + ob1);
            float2 m1 = *(const float2*)(Mraw + (size_t)(r + 8) * 256 + c);
            *(float2*)(out + (size_t)(r + 8) * 256 + c) =
                make_float2(acc[mi][nj][2] + m1.x + ob0, acc[mi][nj][3] + m1.y + ob1);
        }
    }
}

// ---------------------------------------------------------------------------
extern "C" void kernel_launch(void* const* d_in, const int* in_sizes, int n_in,
                              void* d_out, int out_size)
{
    const float* M_raw      = (const float*)d_in[0];
    const float* Z          = (const float*)d_in[1];
    const float* M_mask     = (const float*)d_in[2];
    const float* ln_m_scale = (const float*)d_in[3];
    const float* ln_m_bias  = (const float*)d_in[4];
    const float* ln_z_scale = (const float*)d_in[5];
    const float* ln_z_bias  = (const float*)d_in[6];
    const float* W_b        = (const float*)d_in[7];
    const float* W_qkv      = (const float*)d_in[8];
    const float* W_gate     = (const float*)d_in[9];
    const float* gbias      = (const float*)d_in[10];
    const float* W_o        = (const float*)d_in[11];
    const float* out_bias   = (const float*)d_in[12];
    float* out = (float*)d_out;

    cudaFuncSetAttribute(attn_kernel, cudaFuncAttributeMaxDynamicSharedMemorySize,
                         SMEM_ATTN);
    cudaFuncSetAttribute(gemm_proj_mma, cudaFuncAttributeMaxDynamicSharedMemorySize,
                         PROJ_SMEM);

    ln_m_kernel<<<NROWS, 256>>>(M_raw, ln_m_scale, ln_m_bias);
    wconv_kernel<<<EPROJ, 256>>>(W_qkv, W_gate);
    wconv_o_kernel<<<D_NODE, 256>>>(W_o);
    pair_kernel<<<NRES * NRES, 128>>>(Z, ln_z_scale, ln_z_bias, W_b);
    gemm_proj_mma<<<dim3(EPROJ / 128, NROWS / 128), 256, PROJ_SMEM>>>();
    attn_kernel<<<dim3(NHEAD, NSEQ), 256, SMEM_ATTN>>>(M_mask);
    gemm_out_mma<<<dim3(256 / 128, NROWS / 128), 256>>>(gbias, M_raw, out_bias, out);
}

// round 5
// speedup vs baseline: 2.2932x; 1.3104x over previous
#include <cuda_runtime.h>
#include <cuda_bf16.h>
#include <cstdint>
#include <math.h>

// Problem constants
#define D_NODE 256
#define D_PAIR 128
#define NHEAD  8
#define NSEQ   128
#define NRES   256
#define NROWS  (NSEQ * NRES)          // 32768
#define EPROJ  1024                    // 768 qkv + 256 gate

// Scratch
__device__ __nv_bfloat16 g_Mh[(size_t)NROWS * D_NODE];   // LN(M) hi
__device__ __nv_bfloat16 g_Ml[(size_t)NROWS * D_NODE];   // LN(M) lo
__device__ __nv_bfloat16 g_Wh[(size_t)EPROJ * D_NODE];   // [Wqkv;Wgate] hi
__device__ __nv_bfloat16 g_Wl[(size_t)EPROJ * D_NODE];   // lo
__device__ __nv_bfloat16 g_Oh[(size_t)D_NODE * D_NODE];  // W_o hi
__device__ __nv_bfloat16 g_Ol[(size_t)D_NODE * D_NODE];  // W_o lo
__device__ __nv_bfloat16 g_Xh[(size_t)NROWS * 768];      // q(scaled)|k|v hi
__device__ __nv_bfloat16 g_Xl[(size_t)NROWS * 768];      // lo
__device__ float         g_gate[(size_t)NROWS * 256];    // gate logits fp32
__device__ __nv_bfloat16 g_pbB[(size_t)NHEAD * NRES * NRES]; // pair bias [h][q][k] bf16
__device__ float g_wa[(size_t)NROWS * D_NODE];           // attention output

__device__ __forceinline__ uint32_t smem_u32(const void* p) {
    uint32_t a;
    asm("{ .reg .u64 t; cvta.to.shared.u64 t, %1; cvt.u32.u64 %0, t; }"
        : "=r"(a) : "l"(p));
    return a;
}

#define LDM_X4(r0, r1, r2, r3, addr)                                           \
    asm volatile("ldmatrix.sync.aligned.m8n8.x4.shared.b16 {%0,%1,%2,%3}, [%4];" \
                 : "=r"(r0), "=r"(r1), "=r"(r2), "=r"(r3) : "r"(addr))
#define LDM_A(v, addr) LDM_X4((v)[0], (v)[1], (v)[2], (v)[3], addr)

#define MMA_BF16(d, a, b0, b1)                                                 \
    asm volatile("mma.sync.aligned.m16n8k16.row.col.f32.bf16.bf16.f32 "        \
                 "{%0,%1,%2,%3}, {%4,%5,%6,%7}, {%8,%9}, {%0,%1,%2,%3};"       \
                 : "+f"((d)[0]), "+f"((d)[1]), "+f"((d)[2]), "+f"((d)[3])      \
                 : "r"((a)[0]), "r"((a)[1]), "r"((a)[2]), "r"((a)[3]),         \
                   "r"(b0), "r"(b1))

#define CP16(s, g)                                                             \
    asm volatile("cp.async.cg.shared.global [%0], [%1], 16;" :: "r"(s), "l"(g))
#define CP_COMMIT() asm volatile("cp.async.commit_group;" ::: "memory")

__device__ __forceinline__ uint32_t pk2(float lo, float hi) {
    uint32_t d;
    asm("cvt.rn.bf16x2.f32 %0, %1, %2;" : "=r"(d) : "f"(hi), "f"(lo));
    return d;
}
__device__ __forceinline__ float2 bfu2f2(uint32_t u) {
    __nv_bfloat162 b = *reinterpret_cast<__nv_bfloat162*>(&u);
    return make_float2(__bfloat162float(b.x), __bfloat162float(b.y));
}

__device__ __forceinline__ float warp_sum(float v) {
#pragma unroll
    for (int o = 16; o > 0; o >>= 1) v += __shfl_xor_sync(0xffffffffu, v, o);
    return v;
}

// ---------------------------------------------------------------------------
// Kernel 1: LayerNorm over D_NODE=256 -> bf16 hi/lo split
// ---------------------------------------------------------------------------
__global__ __launch_bounds__(256) void ln_m_kernel(
    const float* __restrict__ x, const float* __restrict__ sc,
    const float* __restrict__ bi)
{
    __shared__ float red[16];
    int row = blockIdx.x;
    int tid = threadIdx.x;
    float v = x[(size_t)row * 256 + tid];
    float s1 = warp_sum(v);
    float s2 = warp_sum(v * v);
    if ((tid & 31) == 0) { red[tid >> 5] = s1; red[8 + (tid >> 5)] = s2; }
    __syncthreads();
    if (tid == 0) {
        float a = 0.f, b = 0.f;
#pragma unroll
        for (int i = 0; i < 8; i++) { a += red[i]; b += red[8 + i]; }
        red[0] = a; red[8] = b;
    }
    __syncthreads();
    float mu  = red[0] * (1.0f / 256.0f);
    float var = red[8] * (1.0f / 256.0f) - mu * mu;
    float inv = rsqrtf(var + 1e-5f);
    float y = (v - mu) * inv * sc[tid] + bi[tid];
    __nv_bfloat16 hi = __float2bfloat16(y);
    g_Mh[(size_t)row * 256 + tid] = hi;
    g_Ml[(size_t)row * 256 + tid] = __float2bfloat16(y - __bfloat162float(hi));
}

// ---------------------------------------------------------------------------
// Kernel 1b/1c: weight conversion -> bf16 hi/lo
// ---------------------------------------------------------------------------
__global__ __launch_bounds__(256) void wconv_kernel(
    const float* __restrict__ Wq, const float* __restrict__ Wg)
{
    int i = blockIdx.x * 256 + threadIdx.x;
    float v = (i < 768 * 256) ? Wq[i] : Wg[i - 768 * 256];
    __nv_bfloat16 hi = __float2bfloat16(v);
    g_Wh[i] = hi;
    g_Wl[i] = __float2bfloat16(v - __bfloat162float(hi));
}

__global__ __launch_bounds__(256) void wconv_o_kernel(const float* __restrict__ Wo)
{
    int i = blockIdx.x * 256 + threadIdx.x;
    float v = Wo[i];
    __nv_bfloat16 hi = __float2bfloat16(v);
    g_Oh[i] = hi;
    g_Ol[i] = __float2bfloat16(v - __bfloat162float(hi));
}

// ---------------------------------------------------------------------------
// Kernel 2: LN(Z) + pair bias -> pbB[h][q][k] (bf16)
// ---------------------------------------------------------------------------
__global__ __launch_bounds__(128) void pair_kernel(
    const float* __restrict__ Z, const float* __restrict__ sc,
    const float* __restrict__ bi, const float* __restrict__ Wb)
{
    __shared__ float red[8];
    __shared__ float zn[128];
    int bid = blockIdx.x;          // = q*256 + k
    int q = bid >> 8, k = bid & 255;
    int tid = threadIdx.x;
    float v = Z[(size_t)bid * 128 + tid];
    float s1 = warp_sum(v);
    float s2 = warp_sum(v * v);
    if ((tid & 31) == 0) { red[tid >> 5] = s1; red[4 + (tid >> 5)] = s2; }
    __syncthreads();
    if (tid == 0) {
        float a = 0.f, b = 0.f;
#pragma unroll
        for (int i = 0; i < 4; i++) { a += red[i]; b += red[4 + i]; }
        red[0] = a; red[4] = b;
    }
    __syncthreads();
    float mu  = red[0] * (1.0f / 128.0f);
    float var = red[4] * (1.0f / 128.0f) - mu * mu;
    zn[tid] = (v - mu) * rsqrtf(var + 1e-5f) * sc[tid] + bi[tid];
    __syncthreads();
    int w = tid >> 5, l = tid & 31;
#pragma unroll
    for (int j = 0; j < 2; j++) {
        int h = w * 2 + j;
        const float* wb = Wb + h * 128;
        float p = zn[l] * wb[l] + zn[l + 32] * wb[l + 32]
                + zn[l + 64] * wb[l + 64] + zn[l + 96] * wb[l + 96];
        p = warp_sum(p);
        if (l == 0) g_pbB[(size_t)h * 65536 + q * 256 + k] = __float2bfloat16(p);
    }
}

// ---------------------------------------------------------------------------
// Kernel 3: projection GEMM (mma.sync bf16 hi/lo, cp.async 2-stage).
// Writes qkv as bf16 hi/lo (q pre-scaled by 1/sqrt(32)); gate as fp32.
// ---------------------------------------------------------------------------
#define OFF_AH 0
#define OFF_AL 10240
#define OFF_BH 20480
#define OFF_BL 30720
#define PROJ_STAGE 40960
#define PROJ_SMEM  (2 * PROJ_STAGE)

__global__ __launch_bounds__(256) void gemm_proj_mma()
{
    extern __shared__ __align__(16) unsigned char smb[];
    uint32_t sbase = smem_u32(smb);
    int tid = threadIdx.x;
    int lane = tid & 31, wid = tid >> 5;
    int wm = wid >> 2, wn = wid & 3;
    int bm = blockIdx.y * 128, bn = blockIdx.x * 128;

    float acc[4][4][4] = {};

    int lrow = tid >> 1, lhalf = tid & 1;
    size_t gA = (size_t)(bm + lrow) * 256 + lhalf * 16;
    size_t gB = (size_t)(bn + lrow) * 256 + lhalf * 16;
    uint32_t sOff = lrow * 80 + lhalf * 32;

    uint32_t aRow = (lane & 15);
    uint32_t aChunk = (lane >> 4) << 3;
    uint32_t bRow = (lane & 7) + ((lane >> 4) << 3);
    uint32_t bChunk = ((lane >> 3) & 1) << 3;

    {
        uint32_t b = sbase;
        CP16(b + OFF_AH + sOff, g_Mh + gA); CP16(b + OFF_AH + sOff + 16, g_Mh + gA + 8);
        CP16(b + OFF_AL + sOff, g_Ml + gA); CP16(b + OFF_AL + sOff + 16, g_Ml + gA + 8);
        CP16(b + OFF_BH + sOff, g_Wh + gB); CP16(b + OFF_BH + sOff + 16, g_Wh + gB + 8);
        CP16(b + OFF_BL + sOff, g_Wl + gB); CP16(b + OFF_BL + sOff + 16, g_Wl + gB + 8);
        CP_COMMIT();
    }

#pragma unroll 1
    for (int t = 0; t < 8; t++) {
        if (t < 7) {
            int c = t + 1;
            uint32_t b = sbase + (c & 1) * PROJ_STAGE;
            const __nv_bfloat16* p;
            p = g_Mh + gA + c * 32;
            CP16(b + OFF_AH + sOff, p); CP16(b + OFF_AH + sOff + 16, p + 8);
            p = g_Ml + gA + c * 32;
            CP16(b + OFF_AL + sOff, p); CP16(b + OFF_AL + sOff + 16, p + 8);
            p = g_Wh + gB + c * 32;
            CP16(b + OFF_BH + sOff, p); CP16(b + OFF_BH + sOff + 16, p + 8);
            p = g_Wl + gB + c * 32;
            CP16(b + OFF_BL + sOff, p); CP16(b + OFF_BL + sOff + 16, p + 8);
            CP_COMMIT();
            asm volatile("cp.async.wait_group 1;" ::: "memory");
        } else {
            asm volatile("cp.async.wait_group 0;" ::: "memory");
        }
        __syncthreads();

        uint32_t sb = sbase + (t & 1) * PROJ_STAGE;
#pragma unroll
        for (int ks = 0; ks < 2; ks++) {
            uint32_t ah[4][4], al[4][4], bh[2][4], bl[2][4];
#pragma unroll
            for (int mi = 0; mi < 4; mi++) {
                uint32_t ad = sb + (wm * 64 + mi * 16 + aRow) * 80
                            + (ks * 16 + aChunk) * 2;
                LDM_A(ah[mi], ad + OFF_AH);
                LDM_A(al[mi], ad + OFF_AL);
            }
#pragma unroll
            for (int ng = 0; ng < 2; ng++) {
                uint32_t bd = sb + (wn * 32 + ng * 16 + bRow) * 80
                            + (ks * 16 + bChunk) * 2;
                LDM_A(bh[ng], bd + OFF_BH);
                LDM_A(bl[ng], bd + OFF_BL);
            }
#pragma unroll
            for (int mi = 0; mi < 4; mi++) {
#pragma unroll
                for (int nj = 0; nj < 4; nj++) {
                    int ng = nj >> 1, sub = (nj & 1) * 2;
                    MMA_BF16(acc[mi][nj], ah[mi], bh[ng][sub], bh[ng][sub + 1]);
                    MMA_BF16(acc[mi][nj], ah[mi], bl[ng][sub], bl[ng][sub + 1]);
                    MMA_BF16(acc[mi][nj], al[mi], bh[ng][sub], bh[ng][sub + 1]);
                }
            }
        }
        __syncthreads();
    }

    int r0 = bm + wm * 64 + (lane >> 2);
    int c0 = bn + wn * 32 + (lane & 3) * 2;
    if (bn < 768) {
        float sc = (bn < 256) ? 0.17677669529663688f : 1.0f;
#pragma unroll
        for (int mi = 0; mi < 4; mi++) {
#pragma unroll
            for (int nj = 0; nj < 4; nj++) {
                int c = c0 + nj * 8;
#pragma unroll
                for (int p = 0; p < 2; p++) {
                    int r = r0 + mi * 16 + p * 8;
                    float v0 = acc[mi][nj][2 * p] * sc;
                    float v1 = acc[mi][nj][2 * p + 1] * sc;
                    __nv_bfloat16 h0 = __float2bfloat16(v0);
                    __nv_bfloat16 h1 = __float2bfloat16(v1);
                    __nv_bfloat162 hh; hh.x = h0; hh.y = h1;
                    __nv_bfloat162 ll;
                    ll.x = __float2bfloat16(v0 - __bfloat162float(h0));
                    ll.y = __float2bfloat16(v1 - __bfloat162float(h1));
                    *(__nv_bfloat162*)(g_Xh + (size_t)r * 768 + c) = hh;
                    *(__nv_bfloat162*)(g_Xl + (size_t)r * 768 + c) = ll;
                }
            }
        }
    } else {
#pragma unroll
        for (int mi = 0; mi < 4; mi++) {
#pragma unroll
            for (int nj = 0; nj < 4; nj++) {
                int c = c0 + nj * 8 - 768;
#pragma unroll
                for (int p = 0; p < 2; p++) {
                    int r = r0 + mi * 16 + p * 8;
                    *(float2*)(g_gate + (size_t)r * 256 + c) =
                        make_float2(acc[mi][nj][2 * p], acc[mi][nj][2 * p + 1]);
                }
            }
        }
    }
}

// ---------------------------------------------------------------------------
// Kernel 4: flash attention via mma.sync. block=(h,s), 256 threads (8 warps),
// warp owns 32 q rows; K-blocks of 64; online softmax in fragment layout.
// ---------------------------------------------------------------------------
#define OQH 0
#define OQL 20480
#define OKH 40960
#define OKL 61440
#define OVH 81920
#define OVL 98816
#define OPB 115712
#define PBSTRIDE 36864
#define OMB 189440
#define ATTN_SMEM 190464

__global__ __launch_bounds__(256) void attn_mma(const float* __restrict__ mask)
{
    extern __shared__ __align__(16) unsigned char smb[];
    uint32_t sb = smem_u32(smb);
    int tid = threadIdx.x;
    int lane = tid & 31, w = tid >> 5;
    int h = blockIdx.x, s = blockIdx.y;

    const __nv_bfloat16* XhB = g_Xh + (size_t)s * 256 * 768;
    const __nv_bfloat16* XlB = g_Xl + (size_t)s * 256 * 768;

    // Q/K tiles via cp.async
#pragma unroll 1
    for (int i = tid; i < 1024; i += 256) {
        int r = i >> 2, seg = i & 3;
        uint32_t d = r * 80 + seg * 16;
        size_t off = (size_t)r * 768 + h * 32 + seg * 8;
        CP16(sb + OQH + d, XhB + off);
        CP16(sb + OQL + d, XlB + off);
        CP16(sb + OKH + d, XhB + off + 256);
        CP16(sb + OKL + d, XlB + off + 256);
    }
    // pb tile kb=0
    {
        const __nv_bfloat16* pbB = g_pbB + (size_t)h * 65536;
#pragma unroll 1
        for (int i = tid; i < 2048; i += 256) {
            int q = i >> 3, seg = i & 7;
            CP16(sb + OPB + q * 144 + seg * 16, pbB + (size_t)q * 256 + seg * 8);
        }
    }
    CP_COMMIT();
    // V transposed (scalar)
    {
        const __nv_bfloat16* vH = XhB + 512 + h * 32;
        const __nv_bfloat16* vL = XlB + 512 + h * 32;
#pragma unroll 1
        for (int i = tid; i < 4096; i += 256) {
            int r = i >> 4, c2 = (i & 15) << 1;
            uint32_t uh = *(const uint32_t*)(vH + (size_t)r * 768 + c2);
            uint32_t ul = *(const uint32_t*)(vL + (size_t)r * 768 + c2);
            __nv_bfloat162 bh = *(__nv_bfloat162*)&uh;
            __nv_bfloat162 bl = *(__nv_bfloat162*)&ul;
            *(__nv_bfloat16*)(smb + OVH + c2 * 528 + r * 2)       = bh.x;
            *(__nv_bfloat16*)(smb + OVH + (c2 + 1) * 528 + r * 2) = bh.y;
            *(__nv_bfloat16*)(smb + OVL + c2 * 528 + r * 2)       = bl.x;
            *(__nv_bfloat16*)(smb + OVL + (c2 + 1) * 528 + r * 2) = bl.y;
        }
    }
    ((float*)(smb + OMB))[tid] = 1e9f * (mask[s * 256 + tid] - 1.0f);
    asm volatile("cp.async.wait_group 0;" ::: "memory");
    __syncthreads();

    uint32_t aRow = lane & 15, aChunk = (lane >> 4) << 3;
    uint32_t bRow = (lane & 7) + ((lane >> 4) << 3);
    uint32_t bChunk = ((lane >> 3) & 1) << 3;

    // hoist Q fragments (constant over kb)
    uint32_t ah[2][2][4], al[2][2][4];
#pragma unroll
    for (int mi = 0; mi < 2; mi++)
#pragma unroll
        for (int ks = 0; ks < 2; ks++) {
            uint32_t ad = sb + (w * 32 + mi * 16 + aRow) * 80 + (ks * 16 + aChunk) * 2;
            LDM_A(ah[mi][ks], ad + OQH);
            LDM_A(al[mi][ks], ad + OQL);
        }

    float o[2][4][4] = {};
    float mrow[4] = {-1e30f, -1e30f, -1e30f, -1e30f};
    float srow[4] = {};

#pragma unroll 1
    for (int kb = 0; kb < 4; kb++) {
        if (kb < 3) {
            const __nv_bfloat16* pbB = g_pbB + (size_t)h * 65536 + (kb + 1) * 64;
            uint32_t dst = sb + OPB + ((kb + 1) & 1) * PBSTRIDE;
#pragma unroll 1
            for (int i = tid; i < 2048; i += 256) {
                int q = i >> 3, seg = i & 7;
                CP16(dst + q * 144 + seg * 16, pbB + (size_t)q * 256 + seg * 8);
            }
            CP_COMMIT();
            asm volatile("cp.async.wait_group 1;" ::: "memory");
        } else {
            asm volatile("cp.async.wait_group 0;" ::: "memory");
        }
        __syncthreads();

        float sfr[2][8][4] = {};
        // S = Q K^T (3-term hi/lo)
#pragma unroll
        for (int ks = 0; ks < 2; ks++)
#pragma unroll
            for (int ng = 0; ng < 4; ng++) {
                uint32_t kh[4], kl[4];
                uint32_t bd = sb + (kb * 64 + ng * 16 + bRow) * 80
                            + (ks * 16 + bChunk) * 2;
                LDM_A(kh, bd + OKH);
                LDM_A(kl, bd + OKL);
#pragma unroll
                for (int mi = 0; mi < 2; mi++) {
                    MMA_BF16(sfr[mi][ng * 2], ah[mi][ks], kh[0], kh[1]);
                    MMA_BF16(sfr[mi][ng * 2], ah[mi][ks], kl[0], kl[1]);
                    MMA_BF16(sfr[mi][ng * 2], al[mi][ks], kh[0], kh[1]);
                    MMA_BF16(sfr[mi][ng * 2 + 1], ah[mi][ks], kh[2], kh[3]);
                    MMA_BF16(sfr[mi][ng * 2 + 1], ah[mi][ks], kl[2], kl[3]);
                    MMA_BF16(sfr[mi][ng * 2 + 1], al[mi][ks], kh[2], kh[3]);
                }
            }

        // add mask bias + pair bias
        uint32_t pbuf = sb + OPB + (kb & 1) * PBSTRIDE;
        const float* mbp = (const float*)(smb + OMB) + kb * 64;
#pragma unroll
        for (int mi = 0; mi < 2; mi++) {
            int q0 = w * 32 + mi * 16 + (lane >> 2);
#pragma unroll
            for (int nj = 0; nj < 8; nj++) {
                int cB = nj * 8 + (lane & 3) * 2;
                float2 mv = *(const float2*)(mbp + cB);
                uint32_t u0, u1;
                asm("ld.shared.b32 %0, [%1];" : "=r"(u0) : "r"(pbuf + q0 * 144 + cB * 2));
                asm("ld.shared.b32 %0, [%1];" : "=r"(u1) : "r"(pbuf + (q0 + 8) * 144 + cB * 2));
                float2 p0 = bfu2f2(u0), p1 = bfu2f2(u1);
                sfr[mi][nj][0] += mv.x + p0.x;
                sfr[mi][nj][1] += mv.y + p0.y;
                sfr[mi][nj][2] += mv.x + p1.x;
                sfr[mi][nj][3] += mv.y + p1.y;
            }
        }

        // online softmax (per row-instance; quad reduction)
#pragma unroll
        for (int mi = 0; mi < 2; mi++)
#pragma unroll
            for (int p = 0; p < 2; p++) {
                int id = mi * 2 + p;
                float mx = mrow[id];
#pragma unroll
                for (int nj = 0; nj < 8; nj++)
                    mx = fmaxf(mx, fmaxf(sfr[mi][nj][2 * p], sfr[mi][nj][2 * p + 1]));
                mx = fmaxf(mx, __shfl_xor_sync(0xffffffffu, mx, 1));
                mx = fmaxf(mx, __shfl_xor_sync(0xffffffffu, mx, 2));
                float es = __expf(mrow[id] - mx);
                mrow[id] = mx;
                float ls = 0.f;
#pragma unroll
                for (int nj = 0; nj < 8; nj++) {
                    float v0 = __expf(sfr[mi][nj][2 * p] - mx);
                    float v1 = __expf(sfr[mi][nj][2 * p + 1] - mx);
                    sfr[mi][nj][2 * p] = v0;
                    sfr[mi][nj][2 * p + 1] = v1;
                    ls += v0 + v1;
                }
                ls += __shfl_xor_sync(0xffffffffu, ls, 1);
                ls += __shfl_xor_sync(0xffffffffu, ls, 2);
                srow[id] = srow[id] * es + ls;
#pragma unroll
                for (int nc = 0; nc < 4; nc++) {
                    o[mi][nc][2 * p] *= es;
                    o[mi][nc][2 * p + 1] *= es;
                }
            }

        // O += P V (V hi/lo 2-term)
#pragma unroll
        for (int t = 0; t < 4; t++) {
            uint32_t pa[2][4];
#pragma unroll
            for (int mi = 0; mi < 2; mi++) {
                pa[mi][0] = pk2(sfr[mi][2 * t][0], sfr[mi][2 * t][1]);
                pa[mi][1] = pk2(sfr[mi][2 * t][2], sfr[mi][2 * t][3]);
                pa[mi][2] = pk2(sfr[mi][2 * t + 1][0], sfr[mi][2 * t + 1][1]);
                pa[mi][3] = pk2(sfr[mi][2 * t + 1][2], sfr[mi][2 * t + 1][3]);
            }
#pragma unroll
            for (int ng = 0; ng < 2; ng++) {
                uint32_t vh[4], vl[4];
                uint32_t vd = (ng * 16 + bRow) * 528 + (kb * 64 + t * 16 + bChunk) * 2;
                LDM_A(vh, sb + OVH + vd);
                LDM_A(vl, sb + OVL + vd);
#pragma unroll
                for (int mi = 0; mi < 2; mi++) {
                    MMA_BF16(o[mi][ng * 2], pa[mi], vh[0], vh[1]);
                    MMA_BF16(o[mi][ng * 2], pa[mi], vl[0], vl[1]);
                    MMA_BF16(o[mi][ng * 2 + 1], pa[mi], vh[2], vh[3]);
                    MMA_BF16(o[mi][ng * 2 + 1], pa[mi], vl[2], vl[3]);
                }
            }
        }
        __syncthreads();
    }

    // epilogue: normalize and store
#pragma unroll
    for (int mi = 0; mi < 2; mi++)
#pragma unroll
        for (int p = 0; p < 2; p++) {
            float inv = 1.0f / srow[mi * 2 + p];
            int r = s * 256 + w * 32 + mi * 16 + (lane >> 2) + p * 8;
#pragma unroll
            for (int nc = 0; nc < 4; nc++) {
                int c = h * 32 + nc * 8 + (lane & 3) * 2;
                *(float2*)(g_wa + (size_t)r * 256 + c) =
                    make_float2(o[mi][nc][2 * p] * inv, o[mi][nc][2 * p + 1] * inv);
            }
        }
}

// ---------------------------------------------------------------------------
// Kernel 5: out = (sigmoid(gate)*wa) @ W_o^T + M_raw + out_bias
// ---------------------------------------------------------------------------
__global__ __launch_bounds__(256) void gemm_out_mma(
    const float* __restrict__ gbias, const float* __restrict__ Mraw,
    const float* __restrict__ obias, float* __restrict__ out)
{
    __shared__ __align__(16) unsigned char smo[40960];
    uint32_t sb = smem_u32(smo);
    int tid = threadIdx.x;
    int lane = tid & 31, wid = tid >> 5;
    int wm = wid >> 2, wn = wid & 3;
    int bm = blockIdx.y * 128, bn = blockIdx.x * 128;

    float acc[4][4][4] = {};

    int lrow = tid >> 1, lhalf = tid & 1;
    uint32_t sOff = lrow * 80 + lhalf * 32;
    size_t rA = (size_t)(bm + lrow);
    size_t gB = (size_t)(bn + lrow) * 256 + lhalf * 16;

    uint32_t aRow = (lane & 15);
    uint32_t aChunk = (lane >> 4) << 3;
    uint32_t bRow = (lane & 7) + ((lane >> 4) << 3);
    uint32_t bChunk = ((lane >> 3) & 1) << 3;

#pragma unroll 1
    for (int t = 0; t < 8; t++) {
        int k0 = t * 32 + lhalf * 16;
        if (t) __syncthreads();
        {
            __align__(16) __nv_bfloat16 hi[16], lo[16];
            const float* wp = g_wa + rA * 256 + k0;
            const float* pp = g_gate + rA * 256 + k0;
            const float* gp = gbias + k0;
#pragma unroll
            for (int i = 0; i < 4; i++) {
                float4 w4 = *(const float4*)(wp + i * 4);
                float4 p4 = *(const float4*)(pp + i * 4);
                float4 g4 = *(const float4*)(gp + i * 4);
                float a0 = w4.x / (1.0f + __expf(-(p4.x + g4.x)));
                float a1 = w4.y / (1.0f + __expf(-(p4.y + g4.y)));
                float a2 = w4.z / (1.0f + __expf(-(p4.z + g4.z)));
                float a3 = w4.w / (1.0f + __expf(-(p4.w + g4.w)));
                __nv_bfloat16 h0 = __float2bfloat16(a0);
                __nv_bfloat16 h1 = __float2bfloat16(a1);
                __nv_bfloat16 h2 = __float2bfloat16(a2);
                __nv_bfloat16 h3 = __float2bfloat16(a3);
                hi[i * 4] = h0; hi[i * 4 + 1] = h1; hi[i * 4 + 2] = h2; hi[i * 4 + 3] = h3;
                lo[i * 4]     = __float2bfloat16(a0 - __bfloat162float(h0));
                lo[i * 4 + 1] = __float2bfloat16(a1 - __bfloat162float(h1));
                lo[i * 4 + 2] = __float2bfloat16(a2 - __bfloat162float(h2));
                lo[i * 4 + 3] = __float2bfloat16(a3 - __bfloat162float(h3));
            }
            *(uint4*)(smo + OFF_AH + sOff)      = *(uint4*)hi;
            *(uint4*)(smo + OFF_AH + sOff + 16) = *(uint4*)(hi + 8);
            *(uint4*)(smo + OFF_AL + sOff)      = *(uint4*)lo;
            *(uint4*)(smo + OFF_AL + sOff + 16) = *(uint4*)(lo + 8);
        }
        {
            const __nv_bfloat16* p = g_Oh + gB + t * 32;
            *(uint4*)(smo + OFF_BH + sOff)      = *(const uint4*)p;
            *(uint4*)(smo + OFF_BH + sOff + 16) = *(const uint4*)(p + 8);
            p = g_Ol + gB + t * 32;
            *(uint4*)(smo + OFF_BL + sOff)      = *(const uint4*)p;
            *(uint4*)(smo + OFF_BL + sOff + 16) = *(const uint4*)(p + 8);
        }
        __syncthreads();

#pragma unroll
        for (int ks = 0; ks < 2; ks++) {
            uint32_t ah[4][4], al[4][4], bh[2][4], bl[2][4];
#pragma unroll
            for (int mi = 0; mi < 4; mi++) {
                uint32_t ad = sb + (wm * 64 + mi * 16 + aRow) * 80
                            + (ks * 16 + aChunk) * 2;
                LDM_A(ah[mi], ad + OFF_AH);
                LDM_A(al[mi], ad + OFF_AL);
            }
#pragma unroll
            for (int ng = 0; ng < 2; ng++) {
                uint32_t bd = sb + (wn * 32 + ng * 16 + bRow) * 80
                            + (ks * 16 + bChunk) * 2;
                LDM_A(bh[ng], bd + OFF_BH);
                LDM_A(bl[ng], bd + OFF_BL);
            }
#pragma unroll
            for (int mi = 0; mi < 4; mi++) {
#pragma unroll
                for (int nj = 0; nj < 4; nj++) {
                    int ng = nj >> 1, sub = (nj & 1) * 2;
                    MMA_BF16(acc[mi][nj], ah[mi], bh[ng][sub], bh[ng][sub + 1]);
                    MMA_BF16(acc[mi][nj], ah[mi], bl[ng][sub], bl[ng][sub + 1]);
                    MMA_BF16(acc[mi][nj], al[mi], bh[ng][sub], bh[ng][sub + 1]);
                }
            }
        }
    }

    int r0 = bm + wm * 64 + (lane >> 2);
    int c0 = bn + wn * 32 + (lane & 3) * 2;
#pragma unroll
    for (int mi = 0; mi < 4; mi++) {
#pragma unroll
        for (int nj = 0; nj < 4; nj++) {
            int r = r0 + mi * 16, c = c0 + nj * 8;
            float ob0 = obias[c], ob1 = obias[c + 1];
            float2 m0 = *(const float2*)(Mraw + (size_t)r * 256 + c);
            *(float2*)(out + (size_t)r * 256 + c) =
                make_float2(acc[mi][nj][0] + m0.x + ob0, acc[mi][nj][1] + m0.y + ob1);
            float2 m1 = *(const float2*)(Mraw + (size_t)(r + 8) * 256 + c);
            *(float2*)(out + (size_t)(r + 8) * 256 + c) =
                make_float2(acc[mi][nj][2] + m1.x + ob0, acc[mi][nj][3] + m1.y + ob1);
        }
    }
}

// ---------------------------------------------------------------------------
extern "C" void kernel_launch(void* const* d_in, const int* in_sizes, int n_in,
                              void* d_out, int out_size)
{
    const float* M_raw      = (const float*)d_in[0];
    const float* Z          = (const float*)d_in[1];
    const float* M_mask     = (const float*)d_in[2];
    const float* ln_m_scale = (const float*)d_in[3];
    const float* ln_m_bias  = (const float*)d_in[4];
    const float* ln_z_scale = (const float*)d_in[5];
    const float* ln_z_bias  = (const float*)d_in[6];
    const float* W_b        = (const float*)d_in[7];
    const float* W_qkv      = (const float*)d_in[8];
    const float* W_gate     = (const float*)d_in[9];
    const float* gbias      = (const float*)d_in[10];
    const float* W_o        = (const float*)d_in[11];
    const float* out_bias   = (const float*)d_in[12];
    float* out = (float*)d_out;

    cudaFuncSetAttribute(gemm_proj_mma, cudaFuncAttributeMaxDynamicSharedMemorySize,
                         PROJ_SMEM);
    cudaFuncSetAttribute(attn_mma, cudaFuncAttributeMaxDynamicSharedMemorySize,
                         ATTN_SMEM);

    ln_m_kernel<<<NROWS, 256>>>(M_raw, ln_m_scale, ln_m_bias);
    wconv_kernel<<<EPROJ, 256>>>(W_qkv, W_gate);
    wconv_o_kernel<<<D_NODE, 256>>>(W_o);
    pair_kernel<<<NRES * NRES, 128>>>(Z, ln_z_scale, ln_z_bias, W_b);
    gemm_proj_mma<<<dim3(EPROJ / 128, NROWS / 128), 256, PROJ_SMEM>>>();
    attn_mma<<<dim3(NHEAD, NSEQ), 256, ATTN_SMEM>>>(M_mask);
    gemm_out_mma<<<dim3(256 / 128, NROWS / 128), 256>>>(gbias, M_raw, out_bias, out);
}

// round 6
// speedup vs baseline: 2.7942x; 1.2185x over previous
#include <cuda_runtime.h>
#include <cuda_bf16.h>
#include <cstdint>
#include <math.h>

// Problem constants
#define D_NODE 256
#define D_PAIR 128
#define NHEAD  8
#define NSEQ   128
#define NRES   256
#define NROWS  (NSEQ * NRES)          // 32768
#define EPROJ  1024                    // 768 qkv + 256 gate

// Scratch
__device__ __nv_bfloat16 g_Mh[(size_t)NROWS * D_NODE];   // LN(M) hi
__device__ __nv_bfloat16 g_Ml[(size_t)NROWS * D_NODE];   // LN(M) lo
__device__ __nv_bfloat16 g_Wh[(size_t)EPROJ * D_NODE];   // [Wqkv;Wgate] hi
__device__ __nv_bfloat16 g_Wl[(size_t)EPROJ * D_NODE];   // lo
__device__ __nv_bfloat16 g_Oh[(size_t)D_NODE * D_NODE];  // W_o hi
__device__ __nv_bfloat16 g_Ol[(size_t)D_NODE * D_NODE];  // W_o lo
__device__ __nv_bfloat16 g_Xh[(size_t)NROWS * 768];      // q(scaled)|k|v hi
__device__ __nv_bfloat16 g_Xl[(size_t)NROWS * 768];      // lo
__device__ float         g_gate[(size_t)NROWS * 256];    // gate logits fp32
__device__ __nv_bfloat16 g_pbB[(size_t)NHEAD * NRES * NRES]; // pair bias [h][q][k] bf16
__device__ float g_wa[(size_t)NROWS * D_NODE];           // attention output

__device__ __forceinline__ uint32_t smem_u32(const void* p) {
    uint32_t a;
    asm("{ .reg .u64 t; cvta.to.shared.u64 t, %1; cvt.u32.u64 %0, t; }"
        : "=r"(a) : "l"(p));
    return a;
}

#define LDM_X4(r0, r1, r2, r3, addr)                                           \
    asm volatile("ldmatrix.sync.aligned.m8n8.x4.shared.b16 {%0,%1,%2,%3}, [%4];" \
                 : "=r"(r0), "=r"(r1), "=r"(r2), "=r"(r3) : "r"(addr))
#define LDM_A(v, addr) LDM_X4((v)[0], (v)[1], (v)[2], (v)[3], addr)

#define LDM_T(v, addr)                                                         \
    asm volatile("ldmatrix.sync.aligned.m8n8.x4.trans.shared.b16 {%0,%1,%2,%3}, [%4];" \
                 : "=r"((v)[0]), "=r"((v)[1]), "=r"((v)[2]), "=r"((v)[3]) : "r"(addr))

#define MMA_BF16(d, a, b0, b1)                                                 \
    asm volatile("mma.sync.aligned.m16n8k16.row.col.f32.bf16.bf16.f32 "        \
                 "{%0,%1,%2,%3}, {%4,%5,%6,%7}, {%8,%9}, {%0,%1,%2,%3};"       \
                 : "+f"((d)[0]), "+f"((d)[1]), "+f"((d)[2]), "+f"((d)[3])      \
                 : "r"((a)[0]), "r"((a)[1]), "r"((a)[2]), "r"((a)[3]),         \
                   "r"(b0), "r"(b1))

#define CP16(s, g)                                                             \
    asm volatile("cp.async.cg.shared.global [%0], [%1], 16;" :: "r"(s), "l"(g))
#define CP_COMMIT() asm volatile("cp.async.commit_group;" ::: "memory")

__device__ __forceinline__ uint32_t pk2(float lo, float hi) {
    uint32_t d;
    asm("cvt.rn.bf16x2.f32 %0, %1, %2;" : "=r"(d) : "f"(hi), "f"(lo));
    return d;
}
__device__ __forceinline__ float2 bfu2f2(uint32_t u) {
    __nv_bfloat162 b = *reinterpret_cast<__nv_bfloat162*>(&u);
    return make_float2(__bfloat162float(b.x), __bfloat162float(b.y));
}

__device__ __forceinline__ float warp_sum(float v) {
#pragma unroll
    for (int o = 16; o > 0; o >>= 1) v += __shfl_xor_sync(0xffffffffu, v, o);
    return v;
}

// ---------------------------------------------------------------------------
// Kernel 1: LayerNorm over D_NODE=256 -> bf16 hi/lo. Warp per row, 8 rows/CTA.
// ---------------------------------------------------------------------------
__global__ __launch_bounds__(256) void ln_m_kernel(
    const float* __restrict__ x, const float* __restrict__ sc,
    const float* __restrict__ bi)
{
    int tid = threadIdx.x;
    int w = tid >> 5, l = tid & 31;
    int row = blockIdx.x * 8 + w;
    const float4* xr = (const float4*)(x + (size_t)row * 256);
    float4 a = xr[l], b = xr[l + 32];
    float s1 = (a.x + a.y) + (a.z + a.w) + (b.x + b.y) + (b.z + b.w);
    float s2 = a.x * a.x + a.y * a.y + a.z * a.z + a.w * a.w
             + b.x * b.x + b.y * b.y + b.z * b.z + b.w * b.w;
    s1 = warp_sum(s1);
    s2 = warp_sum(s2);
    float mu  = s1 * (1.0f / 256.0f);
    float var = s2 * (1.0f / 256.0f) - mu * mu;
    float inv = rsqrtf(var + 1e-5f);

    float4 sa = ((const float4*)sc)[l], sb4 = ((const float4*)sc)[l + 32];
    float4 ba = ((const float4*)bi)[l], bb4 = ((const float4*)bi)[l + 32];

    float ya[4] = { (a.x - mu) * inv * sa.x + ba.x, (a.y - mu) * inv * sa.y + ba.y,
                    (a.z - mu) * inv * sa.z + ba.z, (a.w - mu) * inv * sa.w + ba.w };
    float yb[4] = { (b.x - mu) * inv * sb4.x + bb4.x, (b.y - mu) * inv * sb4.y + bb4.y,
                    (b.z - mu) * inv * sb4.z + bb4.z, (b.w - mu) * inv * sb4.w + bb4.w };

    __nv_bfloat16* mh = g_Mh + (size_t)row * 256;
    __nv_bfloat16* ml = g_Ml + (size_t)row * 256;
#pragma unroll
    for (int g = 0; g < 2; g++) {
        float* y = g ? yb : ya;
        int c = l * 4 + g * 128;
        __nv_bfloat162 h0, h1, l0, l1;
        h0.x = __float2bfloat16(y[0]); h0.y = __float2bfloat16(y[1]);
        h1.x = __float2bfloat16(y[2]); h1.y = __float2bfloat16(y[3]);
        l0.x = __float2bfloat16(y[0] - __bfloat162float(h0.x));
        l0.y = __float2bfloat16(y[1] - __bfloat162float(h0.y));
        l1.x = __float2bfloat16(y[2] - __bfloat162float(h1.x));
        l1.y = __float2bfloat16(y[3] - __bfloat162float(h1.y));
        *(__nv_bfloat162*)(mh + c)     = h0;
        *(__nv_bfloat162*)(mh + c + 2) = h1;
        *(__nv_bfloat162*)(ml + c)     = l0;
        *(__nv_bfloat162*)(ml + c + 2) = l1;
    }
}

// ---------------------------------------------------------------------------
// Kernel 1b/1c: weight conversion -> bf16 hi/lo
// ---------------------------------------------------------------------------
__global__ __launch_bounds__(256) void wconv_kernel(
    const float* __restrict__ Wq, const float* __restrict__ Wg)
{
    int i = blockIdx.x * 256 + threadIdx.x;
    float v = (i < 768 * 256) ? Wq[i] : Wg[i - 768 * 256];
    __nv_bfloat16 hi = __float2bfloat16(v);
    g_Wh[i] = hi;
    g_Wl[i] = __float2bfloat16(v - __bfloat162float(hi));
}

__global__ __launch_bounds__(256) void wconv_o_kernel(const float* __restrict__ Wo)
{
    int i = blockIdx.x * 256 + threadIdx.x;
    float v = Wo[i];
    __nv_bfloat16 hi = __float2bfloat16(v);
    g_Oh[i] = hi;
    g_Ol[i] = __float2bfloat16(v - __bfloat162float(hi));
}

// ---------------------------------------------------------------------------
// Kernel 2: LN(Z) + pair bias -> pbB[h][q][k]. Warp per Z row, 8 rows/CTA.
// ---------------------------------------------------------------------------
__global__ __launch_bounds__(256) void pair_kernel(
    const float* __restrict__ Z, const float* __restrict__ sc,
    const float* __restrict__ bi, const float* __restrict__ Wb)
{
    __shared__ float swb[1024];    // [h][128]
    __shared__ float ssc[128], sbi[128];
    __shared__ float spb[64];      // [row8][h8]
    int tid = threadIdx.x;
    if (tid < 128) { ssc[tid] = sc[tid]; sbi[tid] = bi[tid]; }
    ((float4*)swb)[tid] = ((const float4*)Wb)[tid];
    __syncthreads();

    int w = tid >> 5, l = tid & 31;
    int row = blockIdx.x * 8 + w;          // = q*256 + k
    float4 z = ((const float4*)(Z + (size_t)row * 128))[l];
    float s1 = (z.x + z.y) + (z.z + z.w);
    float s2 = z.x * z.x + z.y * z.y + z.z * z.z + z.w * z.w;
    s1 = warp_sum(s1);
    s2 = warp_sum(s2);
    float mu  = s1 * (1.0f / 128.0f);
    float var = s2 * (1.0f / 128.0f) - mu * mu;
    float inv = rsqrtf(var + 1e-5f);
    int c = l * 4;
    float zn0 = (z.x - mu) * inv * ssc[c]     + sbi[c];
    float zn1 = (z.y - mu) * inv * ssc[c + 1] + sbi[c + 1];
    float zn2 = (z.z - mu) * inv * ssc[c + 2] + sbi[c + 2];
    float zn3 = (z.w - mu) * inv * ssc[c + 3] + sbi[c + 3];
#pragma unroll
    for (int hh = 0; hh < 8; hh++) {
        float4 wb4 = ((const float4*)swb)[hh * 32 + l];
        float p = zn0 * wb4.x + zn1 * wb4.y + zn2 * wb4.z + zn3 * wb4.w;
        p = warp_sum(p);
        if (l == 0) spb[w * 8 + hh] = p;
    }
    __syncthreads();
    if (tid < 64) {
        int hh = tid >> 3, j = tid & 7;
        int row0 = blockIdx.x * 8;
        int q = row0 >> 8, k0 = row0 & 255;
        g_pbB[(size_t)hh * 65536 + q * 256 + k0 + j] = __float2bfloat16(spb[j * 8 + hh]);
    }
}

// ---------------------------------------------------------------------------
// Kernel 3: projection GEMM (mma.sync bf16 hi/lo, cp.async 2-stage).
// ---------------------------------------------------------------------------
#define OFF_AH 0
#define OFF_AL 10240
#define OFF_BH 20480
#define OFF_BL 30720
#define PROJ_STAGE 40960
#define PROJ_SMEM  (2 * PROJ_STAGE)

__global__ __launch_bounds__(256) void gemm_proj_mma()
{
    extern __shared__ __align__(16) unsigned char smb[];
    uint32_t sbase = smem_u32(smb);
    int tid = threadIdx.x;
    int lane = tid & 31, wid = tid >> 5;
    int wm = wid >> 2, wn = wid & 3;
    int bm = blockIdx.y * 128, bn = blockIdx.x * 128;

    float acc[4][4][4] = {};

    int lrow = tid >> 1, lhalf = tid & 1;
    size_t gA = (size_t)(bm + lrow) * 256 + lhalf * 16;
    size_t gB = (size_t)(bn + lrow) * 256 + lhalf * 16;
    uint32_t sOff = lrow * 80 + lhalf * 32;

    uint32_t aRow = (lane & 15);
    uint32_t aChunk = (lane >> 4) << 3;
    uint32_t bRow = (lane & 7) + ((lane >> 4) << 3);
    uint32_t bChunk = ((lane >> 3) & 1) << 3;

    {
        uint32_t b = sbase;
        CP16(b + OFF_AH + sOff, g_Mh + gA); CP16(b + OFF_AH + sOff + 16, g_Mh + gA + 8);
        CP16(b + OFF_AL + sOff, g_Ml + gA); CP16(b + OFF_AL + sOff + 16, g_Ml + gA + 8);
        CP16(b + OFF_BH + sOff, g_Wh + gB); CP16(b + OFF_BH + sOff + 16, g_Wh + gB + 8);
        CP16(b + OFF_BL + sOff, g_Wl + gB); CP16(b + OFF_BL + sOff + 16, g_Wl + gB + 8);
        CP_COMMIT();
    }

#pragma unroll 1
    for (int t = 0; t < 8; t++) {
        if (t < 7) {
            int c = t + 1;
            uint32_t b = sbase + (c & 1) * PROJ_STAGE;
            const __nv_bfloat16* p;
            p = g_Mh + gA + c * 32;
            CP16(b + OFF_AH + sOff, p); CP16(b + OFF_AH + sOff + 16, p + 8);
            p = g_Ml + gA + c * 32;
            CP16(b + OFF_AL + sOff, p); CP16(b + OFF_AL + sOff + 16, p + 8);
            p = g_Wh + gB + c * 32;
            CP16(b + OFF_BH + sOff, p); CP16(b + OFF_BH + sOff + 16, p + 8);
            p = g_Wl + gB + c * 32;
            CP16(b + OFF_BL + sOff, p); CP16(b + OFF_BL + sOff + 16, p + 8);
            CP_COMMIT();
            asm volatile("cp.async.wait_group 1;" ::: "memory");
        } else {
            asm volatile("cp.async.wait_group 0;" ::: "memory");
        }
        __syncthreads();

        uint32_t sb = sbase + (t & 1) * PROJ_STAGE;
#pragma unroll
        for (int ks = 0; ks < 2; ks++) {
            uint32_t ah[4][4], al[4][4], bh[2][4], bl[2][4];
#pragma unroll
            for (int mi = 0; mi < 4; mi++) {
                uint32_t ad = sb + (wm * 64 + mi * 16 + aRow) * 80
                            + (ks * 16 + aChunk) * 2;
                LDM_A(ah[mi], ad + OFF_AH);
                LDM_A(al[mi], ad + OFF_AL);
            }
#pragma unroll
            for (int ng = 0; ng < 2; ng++) {
                uint32_t bd = sb + (wn * 32 + ng * 16 + bRow) * 80
                            + (ks * 16 + bChunk) * 2;
                LDM_A(bh[ng], bd + OFF_BH);
                LDM_A(bl[ng], bd + OFF_BL);
            }
#pragma unroll
            for (int mi = 0; mi < 4; mi++) {
#pragma unroll
                for (int nj = 0; nj < 4; nj++) {
                    int ng = nj >> 1, sub = (nj & 1) * 2;
                    MMA_BF16(acc[mi][nj], ah[mi], bh[ng][sub], bh[ng][sub + 1]);
                    MMA_BF16(acc[mi][nj], ah[mi], bl[ng][sub], bl[ng][sub + 1]);
                    MMA_BF16(acc[mi][nj], al[mi], bh[ng][sub], bh[ng][sub + 1]);
                }
            }
        }
        __syncthreads();
    }

    int r0 = bm + wm * 64 + (lane >> 2);
    int c0 = bn + wn * 32 + (lane & 3) * 2;
    if (bn < 768) {
        float sc = (bn < 256) ? 0.17677669529663688f : 1.0f;
#pragma unroll
        for (int mi = 0; mi < 4; mi++) {
#pragma unroll
            for (int nj = 0; nj < 4; nj++) {
                int c = c0 + nj * 8;
#pragma unroll
                for (int p = 0; p < 2; p++) {
                    int r = r0 + mi * 16 + p * 8;
                    float v0 = acc[mi][nj][2 * p] * sc;
                    float v1 = acc[mi][nj][2 * p + 1] * sc;
                    __nv_bfloat16 h0 = __float2bfloat16(v0);
                    __nv_bfloat16 h1 = __float2bfloat16(v1);
                    __nv_bfloat162 hh; hh.x = h0; hh.y = h1;
                    __nv_bfloat162 ll;
                    ll.x = __float2bfloat16(v0 - __bfloat162float(h0));
                    ll.y = __float2bfloat16(v1 - __bfloat162float(h1));
                    *(__nv_bfloat162*)(g_Xh + (size_t)r * 768 + c) = hh;
                    *(__nv_bfloat162*)(g_Xl + (size_t)r * 768 + c) = ll;
                }
            }
        }
    } else {
#pragma unroll
        for (int mi = 0; mi < 4; mi++) {
#pragma unroll
            for (int nj = 0; nj < 4; nj++) {
                int c = c0 + nj * 8 - 768;
#pragma unroll
                for (int p = 0; p < 2; p++) {
                    int r = r0 + mi * 16 + p * 8;
                    *(float2*)(g_gate + (size_t)r * 256 + c) =
                        make_float2(acc[mi][nj][2 * p], acc[mi][nj][2 * p + 1]);
                }
            }
        }
    }
}

// ---------------------------------------------------------------------------
// Kernel 4: flash attention via mma.sync. block=(h,s), 256 threads (8 warps),
// V loaded in row layout, B-fragments via ldmatrix.trans (no scalar transpose).
// ---------------------------------------------------------------------------
#define OQH 0
#define OQL 20480
#define OKH 40960
#define OKL 61440
#define OVH 81920
#define OVL 102400
#define OPB 122880
#define PBSTRIDE 36864
#define OMB 196608
#define ATTN_SMEM 197632

__global__ __launch_bounds__(256) void attn_mma(const float* __restrict__ mask)
{
    extern __shared__ __align__(16) unsigned char smb[];
    uint32_t sb = smem_u32(smb);
    int tid = threadIdx.x;
    int lane = tid & 31, w = tid >> 5;
    int h = blockIdx.x, s = blockIdx.y;

    const __nv_bfloat16* XhB = g_Xh + (size_t)s * 256 * 768;
    const __nv_bfloat16* XlB = g_Xl + (size_t)s * 256 * 768;

    // Q/K/V tiles via cp.async (identical 80B-stride row layout)
#pragma unroll 1
    for (int i = tid; i < 1024; i += 256) {
        int r = i >> 2, seg = i & 3;
        uint32_t d = r * 80 + seg * 16;
        size_t off = (size_t)r * 768 + h * 32 + seg * 8;
        CP16(sb + OQH + d, XhB + off);
        CP16(sb + OQL + d, XlB + off);
        CP16(sb + OKH + d, XhB + off + 256);
        CP16(sb + OKL + d, XlB + off + 256);
        CP16(sb + OVH + d, XhB + off + 512);
        CP16(sb + OVL + d, XlB + off + 512);
    }
    // pb tile kb=0
    {
        const __nv_bfloat16* pbB = g_pbB + (size_t)h * 65536;
#pragma unroll 1
        for (int i = tid; i < 2048; i += 256) {
            int q = i >> 3, seg = i & 7;
            CP16(sb + OPB + q * 144 + seg * 16, pbB + (size_t)q * 256 + seg * 8);
        }
    }
    CP_COMMIT();
    ((float*)(smb + OMB))[tid] = 1e9f * (mask[s * 256 + tid] - 1.0f);
    asm volatile("cp.async.wait_group 0;" ::: "memory");
    __syncthreads();

    uint32_t aRow = lane & 15, aChunk = (lane >> 4) << 3;
    uint32_t bRow = (lane & 7) + ((lane >> 4) << 3);
    uint32_t bChunk = ((lane >> 3) & 1) << 3;
    // trans-load addressing for V (rows = key index, cols = channel)
    uint32_t vkRow = (lane & 7) + (((lane >> 3) & 1) << 3);
    uint32_t vcCol = (lane >> 4) << 3;

    // hoist Q fragments (constant over kb)
    uint32_t ah[2][2][4], al[2][2][4];
#pragma unroll
    for (int mi = 0; mi < 2; mi++)
#pragma unroll
        for (int ks = 0; ks < 2; ks++) {
            uint32_t ad = sb + (w * 32 + mi * 16 + aRow) * 80 + (ks * 16 + aChunk) * 2;
            LDM_A(ah[mi][ks], ad + OQH);
            LDM_A(al[mi][ks], ad + OQL);
        }

    float o[2][4][4] = {};
    float mrow[4] = {-1e30f, -1e30f, -1e30f, -1e30f};
    float srow[4] = {};

#pragma unroll 1
    for (int kb = 0; kb < 4; kb++) {
        if (kb < 3) {
            const __nv_bfloat16* pbB = g_pbB + (size_t)h * 65536 + (kb + 1) * 64;
            uint32_t dst = sb + OPB + ((kb + 1) & 1) * PBSTRIDE;
#pragma unroll 1
            for (int i = tid; i < 2048; i += 256) {
                int q = i >> 3, seg = i & 7;
                CP16(dst + q * 144 + seg * 16, pbB + (size_t)q * 256 + seg * 8);
            }
            CP_COMMIT();
            asm volatile("cp.async.wait_group 1;" ::: "memory");
        } else {
            asm volatile("cp.async.wait_group 0;" ::: "memory");
        }
        __syncthreads();

        float sfr[2][8][4] = {};
        // S = Q K^T (3-term hi/lo)
#pragma unroll
        for (int ks = 0; ks < 2; ks++)
#pragma unroll
            for (int ng = 0; ng < 4; ng++) {
                uint32_t kh[4], kl[4];
                uint32_t bd = sb + (kb * 64 + ng * 16 + bRow) * 80
                            + (ks * 16 + bChunk) * 2;
                LDM_A(kh, bd + OKH);
                LDM_A(kl, bd + OKL);
#pragma unroll
                for (int mi = 0; mi < 2; mi++) {
                    MMA_BF16(sfr[mi][ng * 2], ah[mi][ks], kh[0], kh[1]);
                    MMA_BF16(sfr[mi][ng * 2], ah[mi][ks], kl[0], kl[1]);
                    MMA_BF16(sfr[mi][ng * 2], al[mi][ks], kh[0], kh[1]);
                    MMA_BF16(sfr[mi][ng * 2 + 1], ah[mi][ks], kh[2], kh[3]);
                    MMA_BF16(sfr[mi][ng * 2 + 1], ah[mi][ks], kl[2], kl[3]);
                    MMA_BF16(sfr[mi][ng * 2 + 1], al[mi][ks], kh[2], kh[3]);
                }
            }

        // add mask bias + pair bias
        uint32_t pbuf = sb + OPB + (kb & 1) * PBSTRIDE;
        const float* mbp = (const float*)(smb + OMB) + kb * 64;
#pragma unroll
        for (int mi = 0; mi < 2; mi++) {
            int q0 = w * 32 + mi * 16 + (lane >> 2);
#pragma unroll
            for (int nj = 0; nj < 8; nj++) {
                int cB = nj * 8 + (lane & 3) * 2;
                float2 mv = *(const float2*)(mbp + cB);
                uint32_t u0, u1;
                asm("ld.shared.b32 %0, [%1];" : "=r"(u0) : "r"(pbuf + q0 * 144 + cB * 2));
                asm("ld.shared.b32 %0, [%1];" : "=r"(u1) : "r"(pbuf + (q0 + 8) * 144 + cB * 2));
                float2 p0 = bfu2f2(u0), p1 = bfu2f2(u1);
                sfr[mi][nj][0] += mv.x + p0.x;
                sfr[mi][nj][1] += mv.y + p0.y;
                sfr[mi][nj][2] += mv.x + p1.x;
                sfr[mi][nj][3] += mv.y + p1.y;
            }
        }

        // online softmax (per row-instance; quad reduction)
#pragma unroll
        for (int mi = 0; mi < 2; mi++)
#pragma unroll
            for (int p = 0; p < 2; p++) {
                int id = mi * 2 + p;
                float mx = mrow[id];
#pragma unroll
                for (int nj = 0; nj < 8; nj++)
                    mx = fmaxf(mx, fmaxf(sfr[mi][nj][2 * p], sfr[mi][nj][2 * p + 1]));
                mx = fmaxf(mx, __shfl_xor_sync(0xffffffffu, mx, 1));
                mx = fmaxf(mx, __shfl_xor_sync(0xffffffffu, mx, 2));
                float es = __expf(mrow[id] - mx);
                mrow[id] = mx;
                float ls = 0.f;
#pragma unroll
                for (int nj = 0; nj < 8; nj++) {
                    float v0 = __expf(sfr[mi][nj][2 * p] - mx);
                    float v1 = __expf(sfr[mi][nj][2 * p + 1] - mx);
                    sfr[mi][nj][2 * p] = v0;
                    sfr[mi][nj][2 * p + 1] = v1;
                    ls += v0 + v1;
                }
                ls += __shfl_xor_sync(0xffffffffu, ls, 1);
                ls += __shfl_xor_sync(0xffffffffu, ls, 2);
                srow[id] = srow[id] * es + ls;
#pragma unroll
                for (int nc = 0; nc < 4; nc++) {
                    o[mi][nc][2 * p] *= es;
                    o[mi][nc][2 * p + 1] *= es;
                }
            }

        // O += P V (V hi/lo 2-term, trans-loaded B fragments)
#pragma unroll
        for (int t = 0; t < 4; t++) {
            uint32_t pa[2][4];
#pragma unroll
            for (int mi = 0; mi < 2; mi++) {
                pa[mi][0] = pk2(sfr[mi][2 * t][0], sfr[mi][2 * t][1]);
                pa[mi][1] = pk2(sfr[mi][2 * t][2], sfr[mi][2 * t][3]);
                pa[mi][2] = pk2(sfr[mi][2 * t + 1][0], sfr[mi][2 * t + 1][1]);
                pa[mi][3] = pk2(sfr[mi][2 * t + 1][2], sfr[mi][2 * t + 1][3]);
            }
#pragma unroll
            for (int ng = 0; ng < 2; ng++) {
                uint32_t vh[4], vl[4];
                uint32_t vd = (kb * 64 + t * 16 + vkRow) * 80 + (ng * 16 + vcCol) * 2;
                LDM_T(vh, sb + OVH + vd);
                LDM_T(vl, sb + OVL + vd);
#pragma unroll
                for (int mi = 0; mi < 2; mi++) {
                    MMA_BF16(o[mi][ng * 2], pa[mi], vh[0], vh[1]);
                    MMA_BF16(o[mi][ng * 2], pa[mi], vl[0], vl[1]);
                    MMA_BF16(o[mi][ng * 2 + 1], pa[mi], vh[2], vh[3]);
                    MMA_BF16(o[mi][ng * 2 + 1], pa[mi], vl[2], vl[3]);
                }
            }
        }
        __syncthreads();
    }

    // epilogue: normalize and store
#pragma unroll
    for (int mi = 0; mi < 2; mi++)
#pragma unroll
        for (int p = 0; p < 2; p++) {
            float inv = 1.0f / srow[mi * 2 + p];
            int r = s * 256 + w * 32 + mi * 16 + (lane >> 2) + p * 8;
#pragma unroll
            for (int nc = 0; nc < 4; nc++) {
                int c = h * 32 + nc * 8 + (lane & 3) * 2;
                *(float2*)(g_wa + (size_t)r * 256 + c) =
                    make_float2(o[mi][nc][2 * p] * inv, o[mi][nc][2 * p + 1] * inv);
            }
        }
}

// ---------------------------------------------------------------------------
// Kernel 5: out = (sigmoid(gate)*wa) @ W_o^T + M_raw + out_bias
// ---------------------------------------------------------------------------
__global__ __launch_bounds__(256) void gemm_out_mma(
    const float* __restrict__ gbias, const float* __restrict__ Mraw,
    const float* __restrict__ obias, float* __restrict__ out)
{
    __shared__ __align__(16) unsigned char smo[40960];
    uint32_t sb = smem_u32(smo);
    int tid = threadIdx.x;
    int lane = tid & 31, wid = tid >> 5;
    int wm = wid >> 2, wn = wid & 3;
    int bm = blockIdx.y * 128, bn = blockIdx.x * 128;

    float acc[4][4][4] = {};

    int lrow = tid >> 1, lhalf = tid & 1;
    uint32_t sOff = lrow * 80 + lhalf * 32;
    size_t rA = (size_t)(bm + lrow);
    size_t gB = (size_t)(bn + lrow) * 256 + lhalf * 16;

    uint32_t aRow = (lane & 15);
    uint32_t aChunk = (lane >> 4) << 3;
    uint32_t bRow = (lane & 7) + ((lane >> 4) << 3);
    uint32_t bChunk = ((lane >> 3) & 1) << 3;

#pragma unroll 1
    for (int t = 0; t < 8; t++) {
        int k0 = t * 32 + lhalf * 16;
        if (t) __syncthreads();
        {
            __align__(16) __nv_bfloat16 hi[16], lo[16];
            const float* wp = g_wa + rA * 256 + k0;
            const float* pp = g_gate + rA * 256 + k0;
            const float* gp = gbias + k0;
#pragma unroll
            for (int i = 0; i < 4; i++) {
                float4 w4 = *(const float4*)(wp + i * 4);
                float4 p4 = *(const float4*)(pp + i * 4);
                float4 g4 = *(const float4*)(gp + i * 4);
                float a0 = w4.x / (1.0f + __expf(-(p4.x + g4.x)));
                float a1 = w4.y / (1.0f + __expf(-(p4.y + g4.y)));
                float a2 = w4.z / (1.0f + __expf(-(p4.z + g4.z)));
                float a3 = w4.w / (1.0f + __expf(-(p4.w + g4.w)));
                __nv_bfloat16 h0 = __float2bfloat16(a0);
                __nv_bfloat16 h1 = __float2bfloat16(a1);
                __nv_bfloat16 h2 = __float2bfloat16(a2);
                __nv_bfloat16 h3 = __float2bfloat16(a3);
                hi[i * 4] = h0; hi[i * 4 + 1] = h1; hi[i * 4 + 2] = h2; hi[i * 4 + 3] = h3;
                lo[i * 4]     = __float2bfloat16(a0 - __bfloat162float(h0));
                lo[i * 4 + 1] = __float2bfloat16(a1 - __bfloat162float(h1));
                lo[i * 4 + 2] = __float2bfloat16(a2 - __bfloat162float(h2));
                lo[i * 4 + 3] = __float2bfloat16(a3 - __bfloat162float(h3));
            }
            *(uint4*)(smo + OFF_AH + sOff)      = *(uint4*)hi;
            *(uint4*)(smo + OFF_AH + sOff + 16) = *(uint4*)(hi + 8);
            *(uint4*)(smo + OFF_AL + sOff)      = *(uint4*)lo;
            *(uint4*)(smo + OFF_AL + sOff + 16) = *(uint4*)(lo + 8);
        }
        {
            const __nv_bfloat16* p = g_Oh + gB + t * 32;
            *(uint4*)(smo + OFF_BH + sOff)      = *(const uint4*)p;
            *(uint4*)(smo + OFF_BH + sOff + 16) = *(const uint4*)(p + 8);
            p = g_Ol + gB + t * 32;
            *(uint4*)(smo + OFF_BL + sOff)      = *(const uint4*)p;
            *(uint4*)(smo + OFF_BL + sOff + 16) = *(const uint4*)(p + 8);
        }
        __syncthreads();

#pragma unroll
        for (int ks = 0; ks < 2; ks++) {
            uint32_t ah[4][4], al[4][4], bh[2][4], bl[2][4];
#pragma unroll
            for (int mi = 0; mi < 4; mi++) {
                uint32_t ad = sb + (wm * 64 + mi * 16 + aRow) * 80
                            + (ks * 16 + aChunk) * 2;
                LDM_A(ah[mi], ad + OFF_AH);
                LDM_A(al[mi], ad + OFF_AL);
            }
#pragma unroll
            for (int ng = 0; ng < 2; ng++) {
                uint32_t bd = sb + (wn * 32 + ng * 16 + bRow) * 80
                            + (ks * 16 + bChunk) * 2;
                LDM_A(bh[ng], bd + OFF_BH);
                LDM_A(bl[ng], bd + OFF_BL);
            }
#pragma unroll
            for (int mi = 0; mi < 4; mi++) {
#pragma unroll
                for (int nj = 0; nj < 4; nj++) {
                    int ng = nj >> 1, sub = (nj & 1) * 2;
                    MMA_BF16(acc[mi][nj], ah[mi], bh[ng][sub], bh[ng][sub + 1]);
                    MMA_BF16(acc[mi][nj], ah[mi], bl[ng][sub], bl[ng][sub + 1]);
                    MMA_BF16(acc[mi][nj], al[mi], bh[ng][sub], bh[ng][sub + 1]);
                }
            }
        }
    }

    int r0 = bm + wm * 64 + (lane >> 2);
    int c0 = bn + wn * 32 + (lane & 3) * 2;
#pragma unroll
    for (int mi = 0; mi < 4; mi++) {
#pragma unroll
        for (int nj = 0; nj < 4; nj++) {
            int r = r0 + mi * 16, c = c0 + nj * 8;
            float ob0 = obias[c], ob1 = obias[c + 1];
            float2 m0 = *(const float2*)(Mraw + (size_t)r * 256 + c);
            *(float2*)(out + (size_t)r * 256 + c) =
                make_float2(acc[mi][nj][0] + m0.x + ob0, acc[mi][nj][1] + m0.y + ob1);
            float2 m1 = *(const float2*)(Mraw + (size_t)(r + 8) * 256 + c);
            *(float2*)(out + (size_t)(r + 8) * 256 + c) =
                make_float2(acc[mi][nj][2] + m1.x + ob0, acc[mi][nj][3] + m1.y + ob1);
        }
    }
}

// ---------------------------------------------------------------------------
extern "C" void kernel_launch(void* const* d_in, const int* in_sizes, int n_in,
                              void* d_out, int out_size)
{
    const float* M_raw      = (const float*)d_in[0];
    const float* Z          = (const float*)d_in[1];
    const float* M_mask     = (const float*)d_in[2];
    const float* ln_m_scale = (const float*)d_in[3];
    const float* ln_m_bias  = (const float*)d_in[4];
    const float* ln_z_scale = (const float*)d_in[5];
    const float* ln_z_bias  = (const float*)d_in[6];
    const float* W_b        = (const float*)d_in[7];
    const float* W_qkv      = (const float*)d_in[8];
    const float* W_gate     = (const float*)d_in[9];
    const float* gbias      = (const float*)d_in[10];
    const float* W_o        = (const float*)d_in[11];
    const float* out_bias   = (const float*)d_in[12];
    float* out = (float*)d_out;

    cudaFuncSetAttribute(gemm_proj_mma, cudaFuncAttributeMaxDynamicSharedMemorySize,
                         PROJ_SMEM);
    cudaFuncSetAttribute(attn_mma, cudaFuncAttributeMaxDynamicSharedMemorySize,
                         ATTN_SMEM);

    ln_m_kernel<<<NROWS / 8, 256>>>(M_raw, ln_m_scale, ln_m_bias);
    wconv_kernel<<<EPROJ, 256>>>(W_qkv, W_gate);
    wconv_o_kernel<<<D_NODE, 256>>>(W_o);
    pair_kernel<<<NRES * NRES / 8, 256>>>(Z, ln_z_scale, ln_z_bias, W_b);
    gemm_proj_mma<<<dim3(EPROJ / 128, NROWS / 128), 256, PROJ_SMEM>>>();
    attn_mma<<<dim3(NHEAD, NSEQ), 256, ATTN_SMEM>>>(M_mask);
    gemm_out_mma<<<dim3(256 / 128, NROWS / 128), 256>>>(gbias, M_raw, out_bias, out);
}

// round 7
// speedup vs baseline: 3.0086x; 1.0767x over previous
#include <cuda_runtime.h>
#include <cuda_bf16.h>
#include <cstdint>
#include <math.h>

// Problem constants
#define D_NODE 256
#define D_PAIR 128
#define NHEAD  8
#define NSEQ   128
#define NRES   256
#define NROWS  (NSEQ * NRES)          // 32768
#define EPROJ  1024                    // 768 qkv + 256 gate

#define LOG2E 1.4426950408889634f

// Scratch
__device__ __nv_bfloat16 g_Mh[(size_t)NROWS * D_NODE];   // LN(M) hi
__device__ __nv_bfloat16 g_Ml[(size_t)NROWS * D_NODE];   // LN(M) lo
__device__ __nv_bfloat16 g_Wh[(size_t)EPROJ * D_NODE];   // [Wqkv;Wgate] hi
__device__ __nv_bfloat16 g_Wl[(size_t)EPROJ * D_NODE];   // lo
__device__ __nv_bfloat16 g_Oh[(size_t)D_NODE * D_NODE];  // W_o hi
__device__ __nv_bfloat16 g_Ol[(size_t)D_NODE * D_NODE];  // W_o lo
__device__ __nv_bfloat16 g_Xh[(size_t)NROWS * 768];      // q(scaled)|k|v hi
__device__ __nv_bfloat16 g_Xl[(size_t)NROWS * 768];      // lo
__device__ float         g_gate[(size_t)NROWS * 256];    // gate logits fp32
__device__ __nv_bfloat16 g_pbB[(size_t)NHEAD * NRES * NRES]; // pair bias*log2e [h][q][k]
__device__ float g_wa[(size_t)NROWS * D_NODE];           // attention output

__device__ __forceinline__ uint32_t smem_u32(const void* p) {
    uint32_t a;
    asm("{ .reg .u64 t; cvta.to.shared.u64 t, %1; cvt.u32.u64 %0, t; }"
        : "=r"(a) : "l"(p));
    return a;
}

#define LDM_X4(r0, r1, r2, r3, addr)                                           \
    asm volatile("ldmatrix.sync.aligned.m8n8.x4.shared.b16 {%0,%1,%2,%3}, [%4];" \
                 : "=r"(r0), "=r"(r1), "=r"(r2), "=r"(r3) : "r"(addr))
#define LDM_A(v, addr) LDM_X4((v)[0], (v)[1], (v)[2], (v)[3], addr)

#define LDM_T(v, addr)                                                         \
    asm volatile("ldmatrix.sync.aligned.m8n8.x4.trans.shared.b16 {%0,%1,%2,%3}, [%4];" \
                 : "=r"((v)[0]), "=r"((v)[1]), "=r"((v)[2]), "=r"((v)[3]) : "r"(addr))

#define MMA_BF16(d, a, b0, b1)                                                 \
    asm volatile("mma.sync.aligned.m16n8k16.row.col.f32.bf16.bf16.f32 "        \
                 "{%0,%1,%2,%3}, {%4,%5,%6,%7}, {%8,%9}, {%0,%1,%2,%3};"       \
                 : "+f"((d)[0]), "+f"((d)[1]), "+f"((d)[2]), "+f"((d)[3])      \
                 : "r"((a)[0]), "r"((a)[1]), "r"((a)[2]), "r"((a)[3]),         \
                   "r"(b0), "r"(b1))

#define CP16(s, g)                                                             \
    asm volatile("cp.async.cg.shared.global [%0], [%1], 16;" :: "r"(s), "l"(g))
#define CP_COMMIT() asm volatile("cp.async.commit_group;" ::: "memory")

__device__ __forceinline__ uint32_t pk2(float lo, float hi) {
    uint32_t d;
    asm("cvt.rn.bf16x2.f32 %0, %1, %2;" : "=r"(d) : "f"(hi), "f"(lo));
    return d;
}
__device__ __forceinline__ float2 bfu2f2(uint32_t u) {
    __nv_bfloat162 b = *reinterpret_cast<__nv_bfloat162*>(&u);
    return make_float2(__bfloat162float(b.x), __bfloat162float(b.y));
}
__device__ __forceinline__ float ex2(float x) {
    float r;
    asm("ex2.approx.f32 %0, %1;" : "=f"(r) : "f"(x));
    return r;
}

__device__ __forceinline__ float warp_sum(float v) {
#pragma unroll
    for (int o = 16; o > 0; o >>= 1) v += __shfl_xor_sync(0xffffffffu, v, o);
    return v;
}

// ---------------------------------------------------------------------------
// Kernel 1 (fused preprocessing): ln_m | wconv | wconv_o | pair
//   blocks [0, 4096): LN(M) warp-per-row
//   blocks [4096, 5120): Wqkv/Wgate hi/lo split
//   blocks [5120, 5376): W_o hi/lo split
//   blocks [5376, 13568): LN(Z) + pair bias (x log2e), fold reduction
// ---------------------------------------------------------------------------
#define PREP_LN  4096
#define PREP_WC  (PREP_LN + 1024)   // 5120
#define PREP_WO  (PREP_WC + 256)    // 5376
#define PREP_TOT (PREP_WO + 8192)   // 13568

__global__ __launch_bounds__(256) void prep_kernel(
    const float* __restrict__ M_raw, const float* __restrict__ mlsc,
    const float* __restrict__ mlbi,
    const float* __restrict__ Wq, const float* __restrict__ Wg,
    const float* __restrict__ Wo,
    const float* __restrict__ Z, const float* __restrict__ zsc,
    const float* __restrict__ zbi, const float* __restrict__ Wb)
{
    __shared__ float swb[1024];    // pair: [h][128]
    __shared__ float ssc[128], sbi[128];
    __shared__ float spb[64];      // pair: [row8][h8]

    int b = blockIdx.x;
    int tid = threadIdx.x;

    if (b < PREP_LN) {
        // ---- LayerNorm(M) -> bf16 hi/lo, warp per row ----
        int w = tid >> 5, l = tid & 31;
        int row = b * 8 + w;
        const float4* xr = (const float4*)(M_raw + (size_t)row * 256);
        float4 a = xr[l], bb = xr[l + 32];
        float s1 = (a.x + a.y) + (a.z + a.w) + (bb.x + bb.y) + (bb.z + bb.w);
        float s2 = a.x * a.x + a.y * a.y + a.z * a.z + a.w * a.w
                 + bb.x * bb.x + bb.y * bb.y + bb.z * bb.z + bb.w * bb.w;
        s1 = warp_sum(s1);
        s2 = warp_sum(s2);
        float mu  = s1 * (1.0f / 256.0f);
        float var = s2 * (1.0f / 256.0f) - mu * mu;
        float inv = rsqrtf(var + 1e-5f);

        float4 sa = ((const float4*)mlsc)[l], sb4 = ((const float4*)mlsc)[l + 32];
        float4 ba = ((const float4*)mlbi)[l], bb4 = ((const float4*)mlbi)[l + 32];

        float ya[4] = { (a.x - mu) * inv * sa.x + ba.x, (a.y - mu) * inv * sa.y + ba.y,
                        (a.z - mu) * inv * sa.z + ba.z, (a.w - mu) * inv * sa.w + ba.w };
        float yb[4] = { (bb.x - mu) * inv * sb4.x + bb4.x, (bb.y - mu) * inv * sb4.y + bb4.y,
                        (bb.z - mu) * inv * sb4.z + bb4.z, (bb.w - mu) * inv * sb4.w + bb4.w };

        __nv_bfloat16* mh = g_Mh + (size_t)row * 256;
        __nv_bfloat16* ml = g_Ml + (size_t)row * 256;
#pragma unroll
        for (int g = 0; g < 2; g++) {
            float* y = g ? yb : ya;
            int c = l * 4 + g * 128;
            __nv_bfloat162 h0, h1, l0, l1;
            h0.x = __float2bfloat16(y[0]); h0.y = __float2bfloat16(y[1]);
            h1.x = __float2bfloat16(y[2]); h1.y = __float2bfloat16(y[3]);
            l0.x = __float2bfloat16(y[0] - __bfloat162float(h0.x));
            l0.y = __float2bfloat16(y[1] - __bfloat162float(h0.y));
            l1.x = __float2bfloat16(y[2] - __bfloat162float(h1.x));
            l1.y = __float2bfloat16(y[3] - __bfloat162float(h1.y));
            *(__nv_bfloat162*)(mh + c)     = h0;
            *(__nv_bfloat162*)(mh + c + 2) = h1;
            *(__nv_bfloat162*)(ml + c)     = l0;
            *(__nv_bfloat162*)(ml + c + 2) = l1;
        }
    } else if (b < PREP_WC) {
        // ---- [Wqkv; Wgate] -> bf16 hi/lo ----
        int i = (b - PREP_LN) * 256 + tid;
        float v = (i < 768 * 256) ? Wq[i] : Wg[i - 768 * 256];
        __nv_bfloat16 hi = __float2bfloat16(v);
        g_Wh[i] = hi;
        g_Wl[i] = __float2bfloat16(v - __bfloat162float(hi));
    } else if (b < PREP_WO) {
        // ---- W_o -> bf16 hi/lo ----
        int i = (b - PREP_WC) * 256 + tid;
        float v = Wo[i];
        __nv_bfloat16 hi = __float2bfloat16(v);
        g_Oh[i] = hi;
        g_Ol[i] = __float2bfloat16(v - __bfloat162float(hi));
    } else {
        // ---- LN(Z) + pair bias (x log2e), warp per Z row, fold reduce ----
        int pb = b - PREP_WO;
        if (tid < 128) { ssc[tid] = zsc[tid]; sbi[tid] = zbi[tid]; }
        ((float4*)swb)[tid] = ((const float4*)Wb)[tid];
        __syncthreads();

        int w = tid >> 5, l = tid & 31;
        int row = pb * 8 + w;                // = q*256 + k
        float4 z = ((const float4*)(Z + (size_t)row * 128))[l];
        float s1 = (z.x + z.y) + (z.z + z.w);
        float s2 = z.x * z.x + z.y * z.y + z.z * z.z + z.w * z.w;
        s1 = warp_sum(s1);
        s2 = warp_sum(s2);
        float mu  = s1 * (1.0f / 128.0f);
        float var = s2 * (1.0f / 128.0f) - mu * mu;
        float inv = rsqrtf(var + 1e-5f);
        int c = l * 4;
        float zn0 = (z.x - mu) * inv * ssc[c]     + sbi[c];
        float zn1 = (z.y - mu) * inv * ssc[c + 1] + sbi[c + 1];
        float zn2 = (z.z - mu) * inv * ssc[c + 2] + sbi[c + 2];
        float zn3 = (z.w - mu) * inv * ssc[c + 3] + sbi[c + 3];

        float p[8];
#pragma unroll
        for (int hh = 0; hh < 8; hh++) {
            float4 wb4 = ((const float4*)swb)[hh * 32 + l];
            p[hh] = zn0 * wb4.x + zn1 * wb4.y + zn2 * wb4.z + zn3 * wb4.w;
        }
        // fold reduction: 8 values -> 1 per lane group (16 shuffles)
#pragma unroll
        for (int hh = 0; hh < 8; hh++) p[hh] += __shfl_xor_sync(0xffffffffu, p[hh], 16);
        float q0 = (l & 16) ? p[4] : p[0];
        float q1 = (l & 16) ? p[5] : p[1];
        float q2 = (l & 16) ? p[6] : p[2];
        float q3 = (l & 16) ? p[7] : p[3];
        q0 += __shfl_xor_sync(0xffffffffu, q0, 8);
        q1 += __shfl_xor_sync(0xffffffffu, q1, 8);
        q2 += __shfl_xor_sync(0xffffffffu, q2, 8);
        q3 += __shfl_xor_sync(0xffffffffu, q3, 8);
        float r0 = (l & 8) ? q2 : q0;
        float r1 = (l & 8) ? q3 : q1;
        r0 += __shfl_xor_sync(0xffffffffu, r0, 4);
        r1 += __shfl_xor_sync(0xffffffffu, r1, 4);
        float s0 = (l & 4) ? r1 : r0;
        s0 += __shfl_xor_sync(0xffffffffu, s0, 2);
        s0 += __shfl_xor_sync(0xffffffffu, s0, 1);
        if ((l & 3) == 0) spb[w * 8 + (l >> 2)] = s0 * LOG2E;
        __syncthreads();
        if (tid < 64) {
            int hh = tid >> 3, j = tid & 7;
            int row0 = pb * 8;
            int qq = row0 >> 8, k0 = row0 & 255;
            g_pbB[(size_t)hh * 65536 + qq * 256 + k0 + j] = __float2bfloat16(spb[j * 8 + hh]);
        }
    }
}

// ---------------------------------------------------------------------------
// Kernel 3: projection GEMM (mma.sync bf16, precision-tiered hi/lo).
//   q/k cols: 3-term; v cols: 2-term (A-hi only); gate cols: 1-term.
//   q pre-scaled by log2e/sqrt(32).
// ---------------------------------------------------------------------------
#define OFF_AH 0
#define OFF_AL 10240
#define OFF_BH 20480
#define OFF_BL 30720
#define PROJ_STAGE 40960
#define PROJ_SMEM  (2 * PROJ_STAGE)

__global__ __launch_bounds__(256) void gemm_proj_mma()
{
    extern __shared__ __align__(16) unsigned char smb[];
    uint32_t sbase = smem_u32(smb);
    int tid = threadIdx.x;
    int lane = tid & 31, wid = tid >> 5;
    int wm = wid >> 2, wn = wid & 3;
    int bm = blockIdx.y * 128, bn = blockIdx.x * 128;
    // cat: 3 = q/k (full 3-term), 2 = v (A-hi x B hi/lo), 1 = gate (hi x hi)
    int cat = (bn < 512) ? 3 : (bn < 768 ? 2 : 1);

    float acc[4][4][4] = {};

    int lrow = tid >> 1, lhalf = tid & 1;
    size_t gA = (size_t)(bm + lrow) * 256 + lhalf * 16;
    size_t gB = (size_t)(bn + lrow) * 256 + lhalf * 16;
    uint32_t sOff = lrow * 80 + lhalf * 32;

    uint32_t aRow = (lane & 15);
    uint32_t aChunk = (lane >> 4) << 3;
    uint32_t bRow = (lane & 7) + ((lane >> 4) << 3);
    uint32_t bChunk = ((lane >> 3) & 1) << 3;

    {
        uint32_t b = sbase;
        CP16(b + OFF_AH + sOff, g_Mh + gA); CP16(b + OFF_AH + sOff + 16, g_Mh + gA + 8);
        if (cat == 3) {
            CP16(b + OFF_AL + sOff, g_Ml + gA); CP16(b + OFF_AL + sOff + 16, g_Ml + gA + 8);
        }
        CP16(b + OFF_BH + sOff, g_Wh + gB); CP16(b + OFF_BH + sOff + 16, g_Wh + gB + 8);
        if (cat >= 2) {
            CP16(b + OFF_BL + sOff, g_Wl + gB); CP16(b + OFF_BL + sOff + 16, g_Wl + gB + 8);
        }
        CP_COMMIT();
    }

#pragma unroll 1
    for (int t = 0; t < 8; t++) {
        if (t < 7) {
            int c = t + 1;
            uint32_t b = sbase + (c & 1) * PROJ_STAGE;
            const __nv_bfloat16* p;
            p = g_Mh + gA + c * 32;
            CP16(b + OFF_AH + sOff, p); CP16(b + OFF_AH + sOff + 16, p + 8);
            if (cat == 3) {
                p = g_Ml + gA + c * 32;
                CP16(b + OFF_AL + sOff, p); CP16(b + OFF_AL + sOff + 16, p + 8);
            }
            p = g_Wh + gB + c * 32;
            CP16(b + OFF_BH + sOff, p); CP16(b + OFF_BH + sOff + 16, p + 8);
            if (cat >= 2) {
                p = g_Wl + gB + c * 32;
                CP16(b + OFF_BL + sOff, p); CP16(b + OFF_BL + sOff + 16, p + 8);
            }
            CP_COMMIT();
            asm volatile("cp.async.wait_group 1;" ::: "memory");
        } else {
            asm volatile("cp.async.wait_group 0;" ::: "memory");
        }
        __syncthreads();

        uint32_t sb = sbase + (t & 1) * PROJ_STAGE;
#pragma unroll
        for (int ks = 0; ks < 2; ks++) {
            uint32_t ah[4][4], al[4][4], bh[2][4], bl[2][4];
#pragma unroll
            for (int mi = 0; mi < 4; mi++) {
                uint32_t ad = sb + (wm * 64 + mi * 16 + aRow) * 80
                            + (ks * 16 + aChunk) * 2;
                LDM_A(ah[mi], ad + OFF_AH);
                if (cat == 3) LDM_A(al[mi], ad + OFF_AL);
            }
#pragma unroll
            for (int ng = 0; ng < 2; ng++) {
                uint32_t bd = sb + (wn * 32 + ng * 16 + bRow) * 80
                            + (ks * 16 + bChunk) * 2;
                LDM_A(bh[ng], bd + OFF_BH);
                if (cat >= 2) LDM_A(bl[ng], bd + OFF_BL);
            }
#pragma unroll
            for (int mi = 0; mi < 4; mi++) {
#pragma unroll
                for (int nj = 0; nj < 4; nj++) {
                    int ng = nj >> 1, sub = (nj & 1) * 2;
                    MMA_BF16(acc[mi][nj], ah[mi], bh[ng][sub], bh[ng][sub + 1]);
                    if (cat >= 2) MMA_BF16(acc[mi][nj], ah[mi], bl[ng][sub], bl[ng][sub + 1]);
                    if (cat == 3) MMA_BF16(acc[mi][nj], al[mi], bh[ng][sub], bh[ng][sub + 1]);
                }
            }
        }
        __syncthreads();
    }

    int r0 = bm + wm * 64 + (lane >> 2);
    int c0 = bn + wn * 32 + (lane & 3) * 2;
    if (bn < 768) {
        float sc = (bn < 256) ? (0.17677669529663688f * LOG2E) : 1.0f;
#pragma unroll
        for (int mi = 0; mi < 4; mi++) {
#pragma unroll
            for (int nj = 0; nj < 4; nj++) {
                int c = c0 + nj * 8;
#pragma unroll
                for (int p = 0; p < 2; p++) {
                    int r = r0 + mi * 16 + p * 8;
                    float v0 = acc[mi][nj][2 * p] * sc;
                    float v1 = acc[mi][nj][2 * p + 1] * sc;
                    __nv_bfloat16 h0 = __float2bfloat16(v0);
                    __nv_bfloat16 h1 = __float2bfloat16(v1);
                    __nv_bfloat162 hh; hh.x = h0; hh.y = h1;
                    __nv_bfloat162 ll;
                    ll.x = __float2bfloat16(v0 - __bfloat162float(h0));
                    ll.y = __float2bfloat16(v1 - __bfloat162float(h1));
                    *(__nv_bfloat162*)(g_Xh + (size_t)r * 768 + c) = hh;
                    *(__nv_bfloat162*)(g_Xl + (size_t)r * 768 + c) = ll;
                }
            }
        }
    } else {
#pragma unroll
        for (int mi = 0; mi < 4; mi++) {
#pragma unroll
            for (int nj = 0; nj < 4; nj++) {
                int c = c0 + nj * 8 - 768;
#pragma unroll
                for (int p = 0; p < 2; p++) {
                    int r = r0 + mi * 16 + p * 8;
                    *(float2*)(g_gate + (size_t)r * 256 + c) =
                        make_float2(acc[mi][nj][2 * p], acc[mi][nj][2 * p + 1]);
                }
            }
        }
    }
}

// ---------------------------------------------------------------------------
// Kernel 4: flash attention via mma.sync (exp2-domain softmax).
// ---------------------------------------------------------------------------
#define OQH 0
#define OQL 20480
#define OKH 40960
#define OKL 61440
#define OVH 81920
#define OVL 102400
#define OPB 122880
#define PBSTRIDE 36864
#define OMB 196608
#define ATTN_SMEM 197632

__global__ __launch_bounds__(256) void attn_mma(const float* __restrict__ mask)
{
    extern __shared__ __align__(16) unsigned char smb[];
    uint32_t sb = smem_u32(smb);
    int tid = threadIdx.x;
    int lane = tid & 31, w = tid >> 5;
    int h = blockIdx.x, s = blockIdx.y;

    const __nv_bfloat16* XhB = g_Xh + (size_t)s * 256 * 768;
    const __nv_bfloat16* XlB = g_Xl + (size_t)s * 256 * 768;

#pragma unroll 1
    for (int i = tid; i < 1024; i += 256) {
        int r = i >> 2, seg = i & 3;
        uint32_t d = r * 80 + seg * 16;
        size_t off = (size_t)r * 768 + h * 32 + seg * 8;
        CP16(sb + OQH + d, XhB + off);
        CP16(sb + OQL + d, XlB + off);
        CP16(sb + OKH + d, XhB + off + 256);
        CP16(sb + OKL + d, XlB + off + 256);
        CP16(sb + OVH + d, XhB + off + 512);
        CP16(sb + OVL + d, XlB + off + 512);
    }
    {
        const __nv_bfloat16* pbB = g_pbB + (size_t)h * 65536;
#pragma unroll 1
        for (int i = tid; i < 2048; i += 256) {
            int q = i >> 3, seg = i & 7;
            CP16(sb + OPB + q * 144 + seg * 16, pbB + (size_t)q * 256 + seg * 8);
        }
    }
    CP_COMMIT();
    ((float*)(smb + OMB))[tid] = (1e9f * LOG2E) * (mask[s * 256 + tid] - 1.0f);
    asm volatile("cp.async.wait_group 0;" ::: "memory");
    __syncthreads();

    uint32_t aRow = lane & 15, aChunk = (lane >> 4) << 3;
    uint32_t bRow = (lane & 7) + ((lane >> 4) << 3);
    uint32_t bChunk = ((lane >> 3) & 1) << 3;
    uint32_t vkRow = (lane & 7) + (((lane >> 3) & 1) << 3);
    uint32_t vcCol = (lane >> 4) << 3;

    uint32_t ah[2][2][4], al[2][2][4];
#pragma unroll
    for (int mi = 0; mi < 2; mi++)
#pragma unroll
        for (int ks = 0; ks < 2; ks++) {
            uint32_t ad = sb + (w * 32 + mi * 16 + aRow) * 80 + (ks * 16 + aChunk) * 2;
            LDM_A(ah[mi][ks], ad + OQH);
            LDM_A(al[mi][ks], ad + OQL);
        }

    float o[2][4][4] = {};
    float mrow[4] = {-1e30f, -1e30f, -1e30f, -1e30f};
    float srow[4] = {};

#pragma unroll 1
    for (int kb = 0; kb < 4; kb++) {
        if (kb < 3) {
            const __nv_bfloat16* pbB = g_pbB + (size_t)h * 65536 + (kb + 1) * 64;
            uint32_t dst = sb + OPB + ((kb + 1) & 1) * PBSTRIDE;
#pragma unroll 1
            for (int i = tid; i < 2048; i += 256) {
                int q = i >> 3, seg = i & 7;
                CP16(dst + q * 144 + seg * 16, pbB + (size_t)q * 256 + seg * 8);
            }
            CP_COMMIT();
            asm volatile("cp.async.wait_group 1;" ::: "memory");
        } else {
            asm volatile("cp.async.wait_group 0;" ::: "memory");
        }
        __syncthreads();

        float sfr[2][8][4] = {};
#pragma unroll
        for (int ks = 0; ks < 2; ks++)
#pragma unroll
            for (int ng = 0; ng < 4; ng++) {
                uint32_t kh[4], kl[4];
                uint32_t bd = sb + (kb * 64 + ng * 16 + bRow) * 80
                            + (ks * 16 + bChunk) * 2;
                LDM_A(kh, bd + OKH);
                LDM_A(kl, bd + OKL);
#pragma unroll
                for (int mi = 0; mi < 2; mi++) {
                    MMA_BF16(sfr[mi][ng * 2], ah[mi][ks], kh[0], kh[1]);
                    MMA_BF16(sfr[mi][ng * 2], ah[mi][ks], kl[0], kl[1]);
                    MMA_BF16(sfr[mi][ng * 2], al[mi][ks], kh[0], kh[1]);
                    MMA_BF16(sfr[mi][ng * 2 + 1], ah[mi][ks], kh[2], kh[3]);
                    MMA_BF16(sfr[mi][ng * 2 + 1], ah[mi][ks], kl[2], kl[3]);
                    MMA_BF16(sfr[mi][ng * 2 + 1], al[mi][ks], kh[2], kh[3]);
                }
            }

        uint32_t pbuf = sb + OPB + (kb & 1) * PBSTRIDE;
        const float* mbp = (const float*)(smb + OMB) + kb * 64;
#pragma unroll
        for (int mi = 0; mi < 2; mi++) {
            int q0 = w * 32 + mi * 16 + (lane >> 2);
#pragma unroll
            for (int nj = 0; nj < 8; nj++) {
                int cB = nj * 8 + (lane & 3) * 2;
                float2 mv = *(const float2*)(mbp + cB);
                uint32_t u0, u1;
                asm("ld.shared.b32 %0, [%1];" : "=r"(u0) : "r"(pbuf + q0 * 144 + cB * 2));
                asm("ld.shared.b32 %0, [%1];" : "=r"(u1) : "r"(pbuf + (q0 + 8) * 144 + cB * 2));
                float2 p0 = bfu2f2(u0), p1 = bfu2f2(u1);
                sfr[mi][nj][0] += mv.x + p0.x;
                sfr[mi][nj][1] += mv.y + p0.y;
                sfr[mi][nj][2] += mv.x + p1.x;
                sfr[mi][nj][3] += mv.y + p1.y;
            }
        }

#pragma unroll
        for (int mi = 0; mi < 2; mi++)
#pragma unroll
            for (int p = 0; p < 2; p++) {
                int id = mi * 2 + p;
                float mx = mrow[id];
#pragma unroll
                for (int nj = 0; nj < 8; nj++)
                    mx = fmaxf(mx, fmaxf(sfr[mi][nj][2 * p], sfr[mi][nj][2 * p + 1]));
                mx = fmaxf(mx, __shfl_xor_sync(0xffffffffu, mx, 1));
                mx = fmaxf(mx, __shfl_xor_sync(0xffffffffu, mx, 2));
                float es = ex2(mrow[id] - mx);
                mrow[id] = mx;
                float ls = 0.f;
#pragma unroll
                for (int nj = 0; nj < 8; nj++) {
                    float v0 = ex2(sfr[mi][nj][2 * p] - mx);
                    float v1 = ex2(sfr[mi][nj][2 * p + 1] - mx);
                    sfr[mi][nj][2 * p] = v0;
                    sfr[mi][nj][2 * p + 1] = v1;
                    ls += v0 + v1;
                }
                ls += __shfl_xor_sync(0xffffffffu, ls, 1);
                ls += __shfl_xor_sync(0xffffffffu, ls, 2);
                srow[id] = srow[id] * es + ls;
#pragma unroll
                for (int nc = 0; nc < 4; nc++) {
                    o[mi][nc][2 * p] *= es;
                    o[mi][nc][2 * p + 1] *= es;
                }
            }

#pragma unroll
        for (int t = 0; t < 4; t++) {
            uint32_t pa[2][4];
#pragma unroll
            for (int mi = 0; mi < 2; mi++) {
                pa[mi][0] = pk2(sfr[mi][2 * t][0], sfr[mi][2 * t][1]);
                pa[mi][1] = pk2(sfr[mi][2 * t][2], sfr[mi][2 * t][3]);
                pa[mi][2] = pk2(sfr[mi][2 * t + 1][0], sfr[mi][2 * t + 1][1]);
                pa[mi][3] = pk2(sfr[mi][2 * t + 1][2], sfr[mi][2 * t + 1][3]);
            }
#pragma unroll
            for (int ng = 0; ng < 2; ng++) {
                uint32_t vh[4], vl[4];
                uint32_t vd = (kb * 64 + t * 16 + vkRow) * 80 + (ng * 16 + vcCol) * 2;
                LDM_T(vh, sb + OVH + vd);
                LDM_T(vl, sb + OVL + vd);
#pragma unroll
                for (int mi = 0; mi < 2; mi++) {
                    MMA_BF16(o[mi][ng * 2], pa[mi], vh[0], vh[1]);
                    MMA_BF16(o[mi][ng * 2], pa[mi], vl[0], vl[1]);
                    MMA_BF16(o[mi][ng * 2 + 1], pa[mi], vh[2], vh[3]);
                    MMA_BF16(o[mi][ng * 2 + 1], pa[mi], vl[2], vl[3]);
                }
            }
        }
        __syncthreads();
    }

#pragma unroll
    for (int mi = 0; mi < 2; mi++)
#pragma unroll
        for (int p = 0; p < 2; p++) {
            float inv = 1.0f / srow[mi * 2 + p];
            int r = s * 256 + w * 32 + mi * 16 + (lane >> 2) + p * 8;
#pragma unroll
            for (int nc = 0; nc < 4; nc++) {
                int c = h * 32 + nc * 8 + (lane & 3) * 2;
                *(float2*)(g_wa + (size_t)r * 256 + c) =
                    make_float2(o[mi][nc][2 * p] * inv, o[mi][nc][2 * p + 1] * inv);
            }
        }
}

// ---------------------------------------------------------------------------
// Kernel 5: out = (sigmoid(gate)*wa) @ W_o^T + M_raw + out_bias
// ---------------------------------------------------------------------------
__global__ __launch_bounds__(256) void gemm_out_mma(
    const float* __restrict__ gbias, const float* __restrict__ Mraw,
    const float* __restrict__ obias, float* __restrict__ out)
{
    __shared__ __align__(16) unsigned char smo[40960];
    uint32_t sb = smem_u32(smo);
    int tid = threadIdx.x;
    int lane = tid & 31, wid = tid >> 5;
    int wm = wid >> 2, wn = wid & 3;
    int bm = blockIdx.y * 128, bn = blockIdx.x * 128;

    float acc[4][4][4] = {};

    int lrow = tid >> 1, lhalf = tid & 1;
    uint32_t sOff = lrow * 80 + lhalf * 32;
    size_t rA = (size_t)(bm + lrow);
    size_t gB = (size_t)(bn + lrow) * 256 + lhalf * 16;

    uint32_t aRow = (lane & 15);
    uint32_t aChunk = (lane >> 4) << 3;
    uint32_t bRow = (lane & 7) + ((lane >> 4) << 3);
    uint32_t bChunk = ((lane >> 3) & 1) << 3;

#pragma unroll 1
    for (int t = 0; t < 8; t++) {
        int k0 = t * 32 + lhalf * 16;
        if (t) __syncthreads();
        {
            __align__(16) __nv_bfloat16 hi[16], lo[16];
            const float* wp = g_wa + rA * 256 + k0;
            const float* pp = g_gate + rA * 256 + k0;
            const float* gp = gbias + k0;
#pragma unroll
            for (int i = 0; i < 4; i++) {
                float4 w4 = *(const float4*)(wp + i * 4);
                float4 p4 = *(const float4*)(pp + i * 4);
                float4 g4 = *(const float4*)(gp + i * 4);
                float a0 = w4.x / (1.0f + __expf(-(p4.x + g4.x)));
                float a1 = w4.y / (1.0f + __expf(-(p4.y + g4.y)));
                float a2 = w4.z / (1.0f + __expf(-(p4.z + g4.z)));
                float a3 = w4.w / (1.0f + __expf(-(p4.w + g4.w)));
                __nv_bfloat16 h0 = __float2bfloat16(a0);
                __nv_bfloat16 h1 = __float2bfloat16(a1);
                __nv_bfloat16 h2 = __float2bfloat16(a2);
                __nv_bfloat16 h3 = __float2bfloat16(a3);
                hi[i * 4] = h0; hi[i * 4 + 1] = h1; hi[i * 4 + 2] = h2; hi[i * 4 + 3] = h3;
                lo[i * 4]     = __float2bfloat16(a0 - __bfloat162float(h0));
                lo[i * 4 + 1] = __float2bfloat16(a1 - __bfloat162float(h1));
                lo[i * 4 + 2] = __float2bfloat16(a2 - __bfloat162float(h2));
                lo[i * 4 + 3] = __float2bfloat16(a3 - __bfloat162float(h3));
            }
            *(uint4*)(smo + OFF_AH + sOff)      = *(uint4*)hi;
            *(uint4*)(smo + OFF_AH + sOff + 16) = *(uint4*)(hi + 8);
            *(uint4*)(smo + OFF_AL + sOff)      = *(uint4*)lo;
            *(uint4*)(smo + OFF_AL + sOff + 16) = *(uint4*)(lo + 8);
        }
        {
            const __nv_bfloat16* p = g_Oh + gB + t * 32;
            *(uint4*)(smo + OFF_BH + sOff)      = *(const uint4*)p;
            *(uint4*)(smo + OFF_BH + sOff + 16) = *(const uint4*)(p + 8);
            p = g_Ol + gB + t * 32;
            *(uint4*)(smo + OFF_BL + sOff)      = *(const uint4*)p;
            *(uint4*)(smo + OFF_BL + sOff + 16) = *(const uint4*)(p + 8);
        }
        __syncthreads();

#pragma unroll
        for (int ks = 0; ks < 2; ks++) {
            uint32_t ah[4][4], al[4][4], bh[2][4], bl[2][4];
#pragma unroll
            for (int mi = 0; mi < 4; mi++) {
                uint32_t ad = sb + (wm * 64 + mi * 16 + aRow) * 80
                            + (ks * 16 + aChunk) * 2;
                LDM_A(ah[mi], ad + OFF_AH);
                LDM_A(al[mi], ad + OFF_AL);
            }
#pragma unroll
            for (int ng = 0; ng < 2; ng++) {
                uint32_t bd = sb + (wn * 32 + ng * 16 + bRow) * 80
                            + (ks * 16 + bChunk) * 2;
                LDM_A(bh[ng], bd + OFF_BH);
                LDM_A(bl[ng], bd + OFF_BL);
            }
#pragma unroll
            for (int mi = 0; mi < 4; mi++) {
#pragma unroll
                for (int nj = 0; nj < 4; nj++) {
                    int ng = nj >> 1, sub = (nj & 1) * 2;
                    MMA_BF16(acc[mi][nj], ah[mi], bh[ng][sub], bh[ng][sub + 1]);
                    MMA_BF16(acc[mi][nj], ah[mi], bl[ng][sub], bl[ng][sub + 1]);
                    MMA_BF16(acc[mi][nj], al[mi], bh[ng][sub], bh[ng][sub + 1]);
                }
            }
        }
    }

    int r0 = bm + wm * 64 + (lane >> 2);
    int c0 = bn + wn * 32 + (lane & 3) * 2;
#pragma unroll
    for (int mi = 0; mi < 4; mi++) {
#pragma unroll
        for (int nj = 0; nj < 4; nj++) {
            int r = r0 + mi * 16, c = c0 + nj * 8;
            float ob0 = obias[c], ob1 = obias[c + 1];
            float2 m0 = *(const float2*)(Mraw + (size_t)r * 256 + c);
            *(float2*)(out + (size_t)r * 256 + c) =
                make_float2(acc[mi][nj][0] + m0.x + ob0, acc[mi][nj][1] + m0.y + ob1);
            float2 m1 = *(const float2*)(Mraw + (size_t)(r + 8) * 256 + c);
            *(float2*)(out + (size_t)(r + 8) * 256 + c) =
                make_float2(acc[mi][nj][2] + m1.x + ob0, acc[mi][nj][3] + m1.y + ob1);
        }
    }
}

// ---------------------------------------------------------------------------
extern "C" void kernel_launch(void* const* d_in, const int* in_sizes, int n_in,
                              void* d_out, int out_size)
{
    const float* M_raw      = (const float*)d_in[0];
    const float* Z          = (const float*)d_in[1];
    const float* M_mask     = (const float*)d_in[2];
    const float* ln_m_scale = (const float*)d_in[3];
    const float* ln_m_bias  = (const float*)d_in[4];
    const float* ln_z_scale = (const float*)d_in[5];
    const float* ln_z_bias  = (const float*)d_in[6];
    const float* W_b        = (const float*)d_in[7];
    const float* W_qkv      = (const float*)d_in[8];
    const float* W_gate     = (const float*)d_in[9];
    const float* gbias      = (const float*)d_in[10];
    const float* W_o        = (const float*)d_in[11];
    const float* out_bias   = (const float*)d_in[12];
    float* out = (float*)d_out;

    cudaFuncSetAttribute(gemm_proj_mma, cudaFuncAttributeMaxDynamicSharedMemorySize,
                         PROJ_SMEM);
    cudaFuncSetAttribute(attn_mma, cudaFuncAttributeMaxDynamicSharedMemorySize,
                         ATTN_SMEM);

    prep_kernel<<<PREP_TOT, 256>>>(M_raw, ln_m_scale, ln_m_bias,
                                   W_qkv, W_gate, W_o,
                                   Z, ln_z_scale, ln_z_bias, W_b);
    gemm_proj_mma<<<dim3(EPROJ / 128, NROWS / 128), 256, PROJ_SMEM>>>();
    attn_mma<<<dim3(NHEAD, NSEQ), 256, ATTN_SMEM>>>(M_mask);
    gemm_out_mma<<<dim3(256 / 128, NROWS / 128), 256>>>(gbias, M_raw, out_bias, out);
}